// round 1
// baseline (speedup 1.0000x reference)
#include <cuda_runtime.h>
#include <cuda_bf16.h>
#include <math.h>

#define NIP       256
#define N_INNER   16
#define NET_DIM   64
#define N_INPUT   784
#define N_CAT     256
#define TWO_PI    6.283185307179586f
#define HIS_PAD   68

// ---------------------------------------------------------------------------
// helpers
// ---------------------------------------------------------------------------
__device__ __forceinline__ float fast_tanh(float x) {
    // tanh(x) = sign(x) * (1 - e)/(1 + e), e = exp(-2|x|); ~1e-6 rel error
    float ax = fabsf(x);
    float e  = __expf(-2.0f * ax);
    float t  = __fdividef(1.0f - e, 1.0f + e);
    return copysignf(t, x);
}

__device__ __forceinline__ float softplus_f(float x) {
    // log(1 + e^x), overflow-safe
    float ax = fabsf(x);
    return fmaxf(x, 0.0f) + log1pf(__expf(-ax));
}

__device__ __forceinline__ float warp_max(float v) {
    #pragma unroll
    for (int o = 16; o > 0; o >>= 1)
        v = fmaxf(v, __shfl_xor_sync(0xffffffffu, v, o));
    return v;
}

__device__ __forceinline__ float warp_sum(float v) {
    #pragma unroll
    for (int o = 16; o > 0; o >>= 1)
        v += __shfl_xor_sync(0xffffffffu, v, o);
    return v;
}

// ---------------------------------------------------------------------------
// Inner net: block = (i, g-half of 8), thread = j (256 threads).
// Computes logits[g][i][j] = -softplus(w2_g . tanh(W1_g @ ff(z_i,z_j))),
// then logsumexp over j (the block) and writes inner_param[g][j][i].
// ---------------------------------------------------------------------------
__global__ void __launch_bounds__(256, 2) inner_kernel(
    const float* __restrict__ z, const float* __restrict__ log_w,
    const float* __restrict__ coeff,   // [2][32]
    const float* __restrict__ w1,      // [1024][64]
    const float* __restrict__ w2,      // [16][64]
    float* __restrict__ out)           // [16][256][256]
{
    __shared__ float c01[64];
    __shared__ float w2s[8 * 64];
    __shared__ float logws[NIP];
    __shared__ float W1s[64 * 64];
    __shared__ float sred[8][8];
    __shared__ float sred2[8][8];

    const int i     = blockIdx.x >> 1;
    const int gbase = (blockIdx.x & 1) * 8;
    const int j     = threadIdx.x;
    const int lane  = j & 31;
    const int wid   = j >> 5;

    if (j < 64) c01[j] = coeff[j];
    logws[j] = log_w[j];
    for (int t = j; t < 8 * 64; t += 256) w2s[t] = w2[gbase * 64 + t];
    __syncthreads();

    const float zi = z[i];
    const float zj = z[j];

    float ff[64];
    #pragma unroll
    for (int k = 0; k < 32; k++) {
        float xp = TWO_PI * fmaf(zi, c01[k], zj * c01[32 + k]);
        float s, c;
        __sincosf(xp, &s, &c);
        ff[k]      = c;
        ff[32 + k] = s;
    }

    float lg[8];
    for (int q = 0; q < 8; q++) {
        __syncthreads();  // previous W1s consumers done
        for (int t = j; t < 64 * 64; t += 256)
            W1s[t] = w1[(gbase + q) * 64 * 64 + t];
        __syncthreads();

        float acc = 0.0f;
        #pragma unroll 4
        for (int d = 0; d < 64; d++) {
            const float4* wrow = (const float4*)&W1s[d * 64];
            float s0 = 0.f, s1 = 0.f, s2 = 0.f, s3 = 0.f;
            #pragma unroll
            for (int t = 0; t < 16; t++) {
                float4 a = wrow[t];   // broadcast LDS.128
                s0 = fmaf(a.x, ff[t * 4 + 0], s0);
                s1 = fmaf(a.y, ff[t * 4 + 1], s1);
                s2 = fmaf(a.z, ff[t * 4 + 2], s2);
                s3 = fmaf(a.w, ff[t * 4 + 3], s3);
            }
            float h = fast_tanh((s0 + s1) + (s2 + s3));
            acc = fmaf(w2s[q * 64 + d], h, acc);
        }
        lg[q] = -softplus_f(acc);
    }
    __syncthreads();

    // batched block logsumexp over j for the 8 g's
    float v[8], m[8];
    #pragma unroll
    for (int u = 0; u < 8; u++) {
        v[u] = lg[u] + logws[j];
        m[u] = warp_max(v[u]);
    }
    if (lane == 0) {
        #pragma unroll
        for (int u = 0; u < 8; u++) sred[u][wid] = m[u];
    }
    __syncthreads();
    #pragma unroll
    for (int u = 0; u < 8; u++) {
        float t = sred[u][0];
        #pragma unroll
        for (int w = 1; w < 8; w++) t = fmaxf(t, sred[u][w]);
        float e  = __expf(v[u] - t);
        float ws = warp_sum(e);
        if (lane == 0) sred2[u][wid] = ws;
        m[u] = t;
    }
    __syncthreads();
    #pragma unroll
    for (int u = 0; u < 8; u++) {
        float s = sred2[u][0];
        #pragma unroll
        for (int w = 1; w < 8; w++) s += sred2[u][w];
        float lse = m[u] + __logf(s);
        // inner_param[g][j][i] = exp(logits + log_w[j] - lse)
        out[(size_t)(gbase + u) * (NIP * NIP) + j * NIP + i] = __expf(v[u] - lse);
    }
}

// ---------------------------------------------------------------------------
// Input net: block = g (784 blocks), 256 threads.
// Stage 1 (thread = n): hi[n][d] = tanh(W1_g[d] . ff(z_n)) into smem.
// Stage 2 (thread = c): logits[c][n] = w2_g[c] . hi[:,n]; log_softmax over c.
// ---------------------------------------------------------------------------
extern __shared__ float s_dyn[];

__global__ void __launch_bounds__(256, 2) input_kernel(
    const float* __restrict__ z,
    const float* __restrict__ coeff,   // [1][32]
    const float* __restrict__ w1,      // [50176][64]
    const float* __restrict__ w2,      // [784][256][64]
    float* __restrict__ out)           // [784][256][256]
{
    float* his   = s_dyn;                     // 256 * HIS_PAD
    float* W1s   = his + NIP * HIS_PAD;       // 4096
    float* ic    = W1s + 4096;                // 32
    float* sred  = ic + 32;                   // 64
    float* sred2 = sred + 64;                 // 64

    const int g    = blockIdx.x;
    const int tid  = threadIdx.x;
    const int lane = tid & 31;
    const int wid  = tid >> 5;

    if (tid < 32) ic[tid] = coeff[tid];
    for (int t = tid; t < 4096; t += 256) W1s[t] = w1[(size_t)g * 4096 + t];
    __syncthreads();

    // ---- stage 1: thread = n ----
    {
        const float zn = z[tid];
        float ff[64];
        #pragma unroll
        for (int k = 0; k < 32; k++) {
            float s, c;
            __sincosf(TWO_PI * zn * ic[k], &s, &c);
            ff[k]      = c;
            ff[32 + k] = s;
        }
        #pragma unroll 4
        for (int d = 0; d < 64; d++) {
            const float4* wrow = (const float4*)&W1s[d * 64];
            float s0 = 0.f, s1 = 0.f, s2 = 0.f, s3 = 0.f;
            #pragma unroll
            for (int t = 0; t < 16; t++) {
                float4 a = wrow[t];
                s0 = fmaf(a.x, ff[t * 4 + 0], s0);
                s1 = fmaf(a.y, ff[t * 4 + 1], s1);
                s2 = fmaf(a.z, ff[t * 4 + 2], s2);
                s3 = fmaf(a.w, ff[t * 4 + 3], s3);
            }
            his[tid * HIS_PAD + d] = fast_tanh((s0 + s1) + (s2 + s3));
        }
    }
    __syncthreads();

    // ---- stage 2: thread = c ----
    const int c = tid;
    float w2r[64];
    #pragma unroll
    for (int t = 0; t < 16; t++) {
        float4 vv = *(const float4*)&w2[((size_t)g * 256 + c) * 64 + t * 4];
        w2r[t * 4 + 0] = vv.x; w2r[t * 4 + 1] = vv.y;
        w2r[t * 4 + 2] = vv.z; w2r[t * 4 + 3] = vv.w;
    }

    float* outg = out + (size_t)g * (NIP * N_CAT);

    for (int n0 = 0; n0 < NIP; n0 += 8) {
        float l[8];
        #pragma unroll
        for (int u = 0; u < 8; u++) l[u] = 0.0f;

        #pragma unroll
        for (int t = 0; t < 16; t++) {
            float a0 = w2r[t * 4 + 0], a1 = w2r[t * 4 + 1];
            float a2 = w2r[t * 4 + 2], a3 = w2r[t * 4 + 3];
            #pragma unroll
            for (int u = 0; u < 8; u++) {
                float4 h4 = *(const float4*)&his[(n0 + u) * HIS_PAD + t * 4]; // broadcast
                l[u] = fmaf(a0, h4.x, fmaf(a1, h4.y, fmaf(a2, h4.z, fmaf(a3, h4.w, l[u]))));
            }
        }

        // log_softmax over c (block-wide), batched for 8 n's
        float m[8];
        #pragma unroll
        for (int u = 0; u < 8; u++) m[u] = warp_max(l[u]);
        if (lane == 0) {
            #pragma unroll
            for (int u = 0; u < 8; u++) sred[u * 8 + wid] = m[u];
        }
        __syncthreads();
        #pragma unroll
        for (int u = 0; u < 8; u++) {
            float t2 = sred[u * 8 + 0];
            #pragma unroll
            for (int w = 1; w < 8; w++) t2 = fmaxf(t2, sred[u * 8 + w]);
            float e  = __expf(l[u] - t2);
            float ws = warp_sum(e);
            if (lane == 0) sred2[u * 8 + wid] = ws;
            m[u] = t2;
        }
        __syncthreads();
        #pragma unroll
        for (int u = 0; u < 8; u++) {
            float ssum = sred2[u * 8 + 0];
            #pragma unroll
            for (int w = 1; w < 8; w++) ssum += sred2[u * 8 + w];
            float lse = m[u] + __logf(ssum);
            outg[(size_t)(n0 + u) * N_CAT + c] = l[u] - lse;
        }
        __syncthreads();  // sred/sred2 reuse in next batch
    }
}

// ---------------------------------------------------------------------------
// launch
// ---------------------------------------------------------------------------
extern "C" void kernel_launch(void* const* d_in, const int* in_sizes, int n_in,
                              void* d_out, int out_size) {
    (void)in_sizes; (void)n_in; (void)out_size;
    const float* z           = (const float*)d_in[0];
    const float* log_w       = (const float*)d_in[1];
    const float* inner_coeff = (const float*)d_in[2];
    const float* inner_w1    = (const float*)d_in[3];
    const float* inner_w2    = (const float*)d_in[4];
    const float* input_coeff = (const float*)d_in[5];
    const float* input_w1    = (const float*)d_in[6];
    const float* input_w2    = (const float*)d_in[7];
    float* out = (float*)d_out;

    const int smem_bytes = (NIP * HIS_PAD + 4096 + 32 + 64 + 64) * (int)sizeof(float);
    cudaFuncSetAttribute(input_kernel,
                         cudaFuncAttributeMaxDynamicSharedMemorySize, smem_bytes);

    inner_kernel<<<512, 256>>>(z, log_w, inner_coeff, inner_w1, inner_w2, out);
    input_kernel<<<N_INPUT, 256, smem_bytes>>>(z, input_coeff, input_w1, input_w2,
                                               out + (size_t)N_INNER * NIP * NIP);
}

// round 3
// speedup vs baseline: 1.5353x; 1.5353x over previous
#include <cuda_runtime.h>
#include <cuda_bf16.h>
#include <math.h>
#include <stdint.h>

#define NIP       256
#define N_INNER   16
#define NET_DIM   64
#define N_INPUT   784
#define N_CAT     256
#define TWO_PI    6.283185307179586f

// input_kernel smem padding (bank-conflict-free, derived in analysis)
#define PADN 264   // his_t rows: 264%32==8 -> banks 8T+g distinct
#define PADC 260   // logits rows: 260%32==4 -> STS banks 8T+g distinct

// ---------------------------------------------------------------------------
// helpers
// ---------------------------------------------------------------------------
__device__ __forceinline__ float fast_tanh(float x) {
    float ax = fabsf(x);
    float e  = __expf(-2.0f * ax);
    float t  = __fdividef(1.0f - e, 1.0f + e);
    return copysignf(t, x);
}

__device__ __forceinline__ float softplus_f(float x) {
    float ax = fabsf(x);
    return fmaxf(x, 0.0f) + log1pf(__expf(-ax));
}

__device__ __forceinline__ float warp_max(float v) {
    #pragma unroll
    for (int o = 16; o > 0; o >>= 1)
        v = fmaxf(v, __shfl_xor_sync(0xffffffffu, v, o));
    return v;
}

__device__ __forceinline__ float warp_sum(float v) {
    #pragma unroll
    for (int o = 16; o > 0; o >>= 1)
        v += __shfl_xor_sync(0xffffffffu, v, o);
    return v;
}

__device__ __forceinline__ uint32_t f2tf32(float x) {
    uint32_t u;
    asm("cvt.rna.tf32.f32 %0, %1;" : "=r"(u) : "f"(x));
    return u;
}

// D += A(16x8,row) * B(8x8,col), tf32 inputs, fp32 accum
__device__ __forceinline__ void mma_tf32(float* c, const uint32_t* a,
                                         uint32_t b0, uint32_t b1) {
    asm volatile(
        "mma.sync.aligned.m16n8k8.row.col.f32.tf32.tf32.f32 "
        "{%0,%1,%2,%3}, {%4,%5,%6,%7}, {%8,%9}, {%0,%1,%2,%3};"
        : "+f"(c[0]), "+f"(c[1]), "+f"(c[2]), "+f"(c[3])
        : "r"(a[0]), "r"(a[1]), "r"(a[2]), "r"(a[3]), "r"(b0), "r"(b1));
}

// ---------------------------------------------------------------------------
// Inner net (unchanged from R1): block = (i, g-half), thread = j.
// ---------------------------------------------------------------------------
__global__ void __launch_bounds__(256, 2) inner_kernel(
    const float* __restrict__ z, const float* __restrict__ log_w,
    const float* __restrict__ coeff,
    const float* __restrict__ w1,
    const float* __restrict__ w2,
    float* __restrict__ out)
{
    __shared__ float c01[64];
    __shared__ float w2s[8 * 64];
    __shared__ float logws[NIP];
    __shared__ float W1s[64 * 64];
    __shared__ float sred[8][8];
    __shared__ float sred2[8][8];

    const int i     = blockIdx.x >> 1;
    const int gbase = (blockIdx.x & 1) * 8;
    const int j     = threadIdx.x;
    const int lane  = j & 31;
    const int wid   = j >> 5;

    if (j < 64) c01[j] = coeff[j];
    logws[j] = log_w[j];
    for (int t = j; t < 8 * 64; t += 256) w2s[t] = w2[gbase * 64 + t];
    __syncthreads();

    const float zi = z[i];
    const float zj = z[j];

    float ff[64];
    #pragma unroll
    for (int k = 0; k < 32; k++) {
        float xp = TWO_PI * fmaf(zi, c01[k], zj * c01[32 + k]);
        float s, c;
        __sincosf(xp, &s, &c);
        ff[k]      = c;
        ff[32 + k] = s;
    }

    float lg[8];
    for (int q = 0; q < 8; q++) {
        __syncthreads();
        for (int t = j; t < 64 * 64; t += 256)
            W1s[t] = w1[(gbase + q) * 64 * 64 + t];
        __syncthreads();

        float acc = 0.0f;
        #pragma unroll 4
        for (int d = 0; d < 64; d++) {
            const float4* wrow = (const float4*)&W1s[d * 64];
            float s0 = 0.f, s1 = 0.f, s2 = 0.f, s3 = 0.f;
            #pragma unroll
            for (int t = 0; t < 16; t++) {
                float4 a = wrow[t];
                s0 = fmaf(a.x, ff[t * 4 + 0], s0);
                s1 = fmaf(a.y, ff[t * 4 + 1], s1);
                s2 = fmaf(a.z, ff[t * 4 + 2], s2);
                s3 = fmaf(a.w, ff[t * 4 + 3], s3);
            }
            float h = fast_tanh((s0 + s1) + (s2 + s3));
            acc = fmaf(w2s[q * 64 + d], h, acc);
        }
        lg[q] = -softplus_f(acc);
    }
    __syncthreads();

    float v[8], m[8];
    #pragma unroll
    for (int u = 0; u < 8; u++) {
        v[u] = lg[u] + logws[j];
        m[u] = warp_max(v[u]);
    }
    if (lane == 0) {
        #pragma unroll
        for (int u = 0; u < 8; u++) sred[u][wid] = m[u];
    }
    __syncthreads();
    #pragma unroll
    for (int u = 0; u < 8; u++) {
        float t = sred[u][0];
        #pragma unroll
        for (int w = 1; w < 8; w++) t = fmaxf(t, sred[u][w]);
        float e  = __expf(v[u] - t);
        float ws = warp_sum(e);
        if (lane == 0) sred2[u][wid] = ws;
        m[u] = t;
    }
    __syncthreads();
    #pragma unroll
    for (int u = 0; u < 8; u++) {
        float s = sred2[u][0];
        #pragma unroll
        for (int w = 1; w < 8; w++) s += sred2[u][w];
        float lse = m[u] + __logf(s);
        out[(size_t)(gbase + u) * (NIP * NIP) + j * NIP + i] = __expf(v[u] - lse);
    }
}

// ---------------------------------------------------------------------------
// Input net, tensor-core version. Block = g, 512 threads (16 warps).
// Stage 1: his_t[k][n] = tf32(tanh(W1_g @ ff(z_n)))  (transposed, padded)
// Stage 2: per warp 16 c-rows; A = W2_g fragments in registers (whole k=64);
//          8 passes of 32 n: mma -> logits smem tile -> log_softmax -> out.
// ---------------------------------------------------------------------------
extern __shared__ float s_dyn[];

__global__ void __launch_bounds__(512) input_kernel(
    const float* __restrict__ z,
    const float* __restrict__ coeff,   // [32]
    const float* __restrict__ w1,      // [784*64][64]
    const float* __restrict__ w2,      // [784][256][64]
    float* __restrict__ out)           // [784][256][256]
{
    float* his    = s_dyn;                 // 64 * PADN floats (tf32 bits)
    float* logits = s_dyn + 64 * PADN;     // 32 * PADC floats (aliases W1s)
    float* W1s    = logits;                // 4096 floats, stage-1 only
    __shared__ float ic[32];

    const int g    = blockIdx.x;
    const int tid  = threadIdx.x;
    const int lane = tid & 31;
    const int warp = tid >> 5;

    if (tid < 32) ic[tid] = coeff[tid];
    for (int t = tid; t < 4096; t += 512) W1s[t] = w1[(size_t)g * 4096 + t];
    __syncthreads();

    // ---- stage 1: thread (n, d-half) ----
    {
        const int n  = tid & 255;
        const int dh = tid >> 8;           // 0 or 1
        const float zn = z[n];
        float ff[64];
        #pragma unroll
        for (int k = 0; k < 32; k++) {
            float s, c;
            __sincosf(TWO_PI * zn * ic[k], &s, &c);
            ff[k]      = c;
            ff[32 + k] = s;
        }
        uint32_t* hisU = (uint32_t*)his;
        #pragma unroll 4
        for (int d = dh * 32; d < dh * 32 + 32; d++) {
            const float4* wrow = (const float4*)&W1s[d * 64];
            float s0 = 0.f, s1 = 0.f, s2 = 0.f, s3 = 0.f;
            #pragma unroll
            for (int t = 0; t < 16; t++) {
                float4 a = wrow[t];
                s0 = fmaf(a.x, ff[t * 4 + 0], s0);
                s1 = fmaf(a.y, ff[t * 4 + 1], s1);
                s2 = fmaf(a.z, ff[t * 4 + 2], s2);
                s3 = fmaf(a.w, ff[t * 4 + 3], s3);
            }
            float h = fast_tanh((s0 + s1) + (s2 + s3));
            hisU[d * PADN + n] = f2tf32(h);
        }
    }
    __syncthreads();   // his_t complete; W1s region now free for logits

    // ---- stage 2 ----
    const int gq = lane >> 2;      // 0..7
    const int T  = lane & 3;       // 0..3
    const int cbase = warp * 16;   // warp owns c in [cbase, cbase+16)

    // A fragments: W2_g rows cbase..cbase+15, all k (8 k-tiles), tf32
    uint32_t A[8][4];
    {
        const float* w2g = w2 + (size_t)g * 256 * 64;
        #pragma unroll
        for (int kk = 0; kk < 8; kk++) {
            A[kk][0] = f2tf32(w2g[(cbase + gq)     * 64 + kk * 8 + T]);
            A[kk][1] = f2tf32(w2g[(cbase + 8 + gq) * 64 + kk * 8 + T]);
            A[kk][2] = f2tf32(w2g[(cbase + gq)     * 64 + kk * 8 + T + 4]);
            A[kk][3] = f2tf32(w2g[(cbase + 8 + gq) * 64 + kk * 8 + T + 4]);
        }
    }

    const uint32_t* hisU = (const uint32_t*)his;
    float* outg = out + (size_t)g * (NIP * N_CAT);

    for (int pass = 0; pass < 8; pass++) {
        const int n0 = pass * 32;

        float acc[4][4];
        #pragma unroll
        for (int nt = 0; nt < 4; nt++)
            #pragma unroll
            for (int u = 0; u < 4; u++) acc[nt][u] = 0.0f;

        #pragma unroll
        for (int kk = 0; kk < 8; kk++) {
            uint32_t B0[4], B1[4];
            #pragma unroll
            for (int nt = 0; nt < 4; nt++) {
                const int ncol = n0 + nt * 8 + gq;
                B0[nt] = hisU[(kk * 8 + T)     * PADN + ncol];
                B1[nt] = hisU[(kk * 8 + T + 4) * PADN + ncol];
            }
            #pragma unroll
            for (int nt = 0; nt < 4; nt++)
                mma_tf32(acc[nt], A[kk], B0[nt], B1[nt]);
        }

        // scatter acc -> logits[nlocal][c]
        #pragma unroll
        for (int nt = 0; nt < 4; nt++) {
            const int nl = nt * 8 + 2 * T;
            logits[nl       * PADC + cbase + gq]     = acc[nt][0];
            logits[(nl + 1) * PADC + cbase + gq]     = acc[nt][1];
            logits[nl       * PADC + cbase + 8 + gq] = acc[nt][2];
            logits[(nl + 1) * PADC + cbase + 8 + gq] = acc[nt][3];
        }
        __syncthreads();

        // epilogue: thread -> (nl = tid>>4, sub = tid&15), 32 c per thread
        {
            const int nl  = tid >> 4;
            const int sub = tid & 15;
            const float* row = logits + nl * PADC;

            float4 v[4];
            float mx = -1e30f;
            #pragma unroll
            for (int i = 0; i < 4; i++) {
                v[i] = *(const float4*)(row + i * 64 + sub * 4);
                mx = fmaxf(mx, fmaxf(fmaxf(v[i].x, v[i].y), fmaxf(v[i].z, v[i].w)));
            }
            #pragma unroll
            for (int o = 1; o < 16; o <<= 1)
                mx = fmaxf(mx, __shfl_xor_sync(0xffffffffu, mx, o));

            float se = 0.0f;
            #pragma unroll
            for (int i = 0; i < 4; i++) {
                se += __expf(v[i].x - mx) + __expf(v[i].y - mx)
                    + __expf(v[i].z - mx) + __expf(v[i].w - mx);
            }
            #pragma unroll
            for (int o = 1; o < 16; o <<= 1)
                se += __shfl_xor_sync(0xffffffffu, se, o);

            const float lse = mx + __logf(se);
            float* orow = outg + (size_t)(n0 + nl) * N_CAT;
            #pragma unroll
            for (int i = 0; i < 4; i++) {
                float4 o4;
                o4.x = v[i].x - lse; o4.y = v[i].y - lse;
                o4.z = v[i].z - lse; o4.w = v[i].w - lse;
                *(float4*)(orow + i * 64 + sub * 4) = o4;
            }
        }
        __syncthreads();   // logits tile reused next pass
    }
}

// ---------------------------------------------------------------------------
// launch
// ---------------------------------------------------------------------------
extern "C" void kernel_launch(void* const* d_in, const int* in_sizes, int n_in,
                              void* d_out, int out_size) {
    (void)in_sizes; (void)n_in; (void)out_size;
    const float* z           = (const float*)d_in[0];
    const float* log_w       = (const float*)d_in[1];
    const float* inner_coeff = (const float*)d_in[2];
    const float* inner_w1    = (const float*)d_in[3];
    const float* inner_w2    = (const float*)d_in[4];
    const float* input_coeff = (const float*)d_in[5];
    const float* input_w1    = (const float*)d_in[6];
    const float* input_w2    = (const float*)d_in[7];
    float* out = (float*)d_out;

    const int smem_bytes = (64 * PADN + 32 * PADC) * (int)sizeof(float);
    cudaFuncSetAttribute(input_kernel,
                         cudaFuncAttributeMaxDynamicSharedMemorySize, smem_bytes);

    inner_kernel<<<512, 256>>>(z, log_w, inner_coeff, inner_w1, inner_w2, out);
    input_kernel<<<N_INPUT, 512, smem_bytes>>>(z, input_coeff, input_w1, input_w2,
                                               out + (size_t)N_INNER * NIP * NIP);
}

// round 4
// speedup vs baseline: 2.5701x; 1.6740x over previous
#include <cuda_runtime.h>
#include <cuda_bf16.h>
#include <math.h>
#include <stdint.h>

#define NIP       256
#define N_INNER   16
#define NET_DIM   64
#define N_INPUT   784
#define N_CAT     256
#define TWO_PI    6.283185307179586f

#define PADN 264   // tf32 tile row pitch: 264%32==8 -> banks 8T+gq distinct
#define PADC 260   // logits rows (input kernel)

// ---------------------------------------------------------------------------
// helpers
// ---------------------------------------------------------------------------
__device__ __forceinline__ float tanha(float x) {
    float y;
    asm("tanh.approx.f32 %0, %1;" : "=f"(y) : "f"(x));
    return y;
}

__device__ __forceinline__ float softplus_f(float x) {
    float ax = fabsf(x);
    return fmaxf(x, 0.0f) + log1pf(__expf(-ax));
}

__device__ __forceinline__ float warp_max(float v) {
    #pragma unroll
    for (int o = 16; o > 0; o >>= 1)
        v = fmaxf(v, __shfl_xor_sync(0xffffffffu, v, o));
    return v;
}

__device__ __forceinline__ float warp_sum(float v) {
    #pragma unroll
    for (int o = 16; o > 0; o >>= 1)
        v += __shfl_xor_sync(0xffffffffu, v, o);
    return v;
}

__device__ __forceinline__ uint32_t f2tf32(float x) {
    uint32_t u;
    asm("cvt.rna.tf32.f32 %0, %1;" : "=r"(u) : "f"(x));
    return u;
}

// D += A(16x8,row) * B(8x8,col), tf32 inputs, fp32 accum
__device__ __forceinline__ void mma_tf32(float* c, const uint32_t* a,
                                         uint32_t b0, uint32_t b1) {
    asm volatile(
        "mma.sync.aligned.m16n8k8.row.col.f32.tf32.tf32.f32 "
        "{%0,%1,%2,%3}, {%4,%5,%6,%7}, {%8,%9}, {%0,%1,%2,%3};"
        : "+f"(c[0]), "+f"(c[1]), "+f"(c[2]), "+f"(c[3])
        : "r"(a[0]), "r"(a[1]), "r"(a[2]), "r"(a[3]), "r"(b0), "r"(b1));
}

extern __shared__ float s_dyn[];

// ---------------------------------------------------------------------------
// Inner net, tensor-core version. Block = i (256), 512 threads, warp = g.
// Phase 0: fft[k][j] = tf32 fourier features for (z_i, z_j), j=0..255.
// Phase 1 (warp g): H = tanh(W1_g @ ff) via mma, dot with w2_g in-fragment,
//                   shfl-reduce over d-lanes, -softplus + log_w -> smem.
// Epilogue (warp g): logsumexp over j, write exp(v-lse) to out[g][j][i].
// ---------------------------------------------------------------------------
__global__ void __launch_bounds__(512, 1) inner_kernel(
    const float* __restrict__ z, const float* __restrict__ log_w,
    const float* __restrict__ coeff,   // [2][32]
    const float* __restrict__ w1,      // [1024][64]
    const float* __restrict__ w2,      // [16][64]
    float* __restrict__ out)           // [16][256][256]
{
    uint32_t* fftU     = (uint32_t*)s_dyn;            // 64 * PADN
    float*    logits_s = s_dyn + 64 * PADN;           // 16 * 256
    float*    logw_s   = logits_s + 16 * 256;         // 256
    float*    cc       = logw_s + 256;                // 64

    const int i    = blockIdx.x;
    const int tid  = threadIdx.x;
    const int lane = tid & 31;
    const int warp = tid >> 5;

    if (tid < 64) cc[tid] = coeff[tid];
    if (tid < 256) logw_s[tid] = log_w[tid];
    __syncthreads();

    // ---- phase 0: fourier features ----
    {
        const int j  = tid & 255;
        const int kh = tid >> 8;          // 0 or 1 -> k range
        const float zi = z[i];
        const float zj = z[j];
        #pragma unroll
        for (int k = kh * 16; k < kh * 16 + 16; k++) {
            float ang = TWO_PI * fmaf(zi, cc[k], zj * cc[32 + k]);
            float s, c;
            __sincosf(ang, &s, &c);
            fftU[k * PADN + j]        = f2tf32(c);
            fftU[(k + 32) * PADN + j] = f2tf32(s);
        }
    }
    __syncthreads();

    // ---- phase 1: per-warp g ----
    const int g  = warp;
    const int gq = lane >> 2;
    const int T  = lane & 3;
    const float* w1g = w1 + g * (NET_DIM * NET_DIM);
    const float* w2g = w2 + g * NET_DIM;

    for (int h = 0; h < 2; h++) {          // j halves of 128
        float plog[32];
        #pragma unroll
        for (int e = 0; e < 32; e++) plog[e] = 0.0f;

        for (int mt = 0; mt < 4; mt++) {   // d tiles of 16
            uint32_t A[8][4];
            const int r0 = mt * 16 + gq;
            const int r1 = mt * 16 + 8 + gq;
            #pragma unroll
            for (int kk = 0; kk < 8; kk++) {
                A[kk][0] = f2tf32(w1g[r0 * 64 + kk * 8 + T]);
                A[kk][1] = f2tf32(w1g[r1 * 64 + kk * 8 + T]);
                A[kk][2] = f2tf32(w1g[r0 * 64 + kk * 8 + T + 4]);
                A[kk][3] = f2tf32(w1g[r1 * 64 + kk * 8 + T + 4]);
            }
            const float w2a = w2g[mt * 16 + gq];
            const float w2b = w2g[mt * 16 + 8 + gq];

            #pragma unroll
            for (int ntp = 0; ntp < 8; ntp++) {   // 2 n-tiles (16 j) per iter
                const int j0 = (h * 16 + ntp * 2) * 8;
                float acc0[4] = {0.f, 0.f, 0.f, 0.f};
                float acc1[4] = {0.f, 0.f, 0.f, 0.f};
                #pragma unroll
                for (int kk = 0; kk < 8; kk++) {
                    uint32_t B0a = fftU[(kk * 8 + T)     * PADN + j0 + gq];
                    uint32_t B1a = fftU[(kk * 8 + T + 4) * PADN + j0 + gq];
                    uint32_t B0b = fftU[(kk * 8 + T)     * PADN + j0 + 8 + gq];
                    uint32_t B1b = fftU[(kk * 8 + T + 4) * PADN + j0 + 8 + gq];
                    mma_tf32(acc0, A[kk], B0a, B1a);
                    mma_tf32(acc1, A[kk], B0b, B1b);
                }
                plog[ntp * 4 + 0] += w2a * tanha(acc0[0]) + w2b * tanha(acc0[2]);
                plog[ntp * 4 + 1] += w2a * tanha(acc0[1]) + w2b * tanha(acc0[3]);
                plog[ntp * 4 + 2] += w2a * tanha(acc1[0]) + w2b * tanha(acc1[2]);
                plog[ntp * 4 + 3] += w2a * tanha(acc1[1]) + w2b * tanha(acc1[3]);
            }
        }

        // reduce over d-lanes (gq = lane bits 2..4) and store v = lg + log_w
        #pragma unroll
        for (int e = 0; e < 32; e++) {
            float v = plog[e];
            v += __shfl_xor_sync(0xffffffffu, v, 4);
            v += __shfl_xor_sync(0xffffffffu, v, 8);
            v += __shfl_xor_sync(0xffffffffu, v, 16);
            if (lane < 4) {
                const int j = (h * 16 + (e >> 1)) * 8 + 2 * T + (e & 1);
                logits_s[g * 256 + j] = -softplus_f(v) + logw_s[j];
            }
        }
    }
    __syncwarp();

    // ---- epilogue: per-warp logsumexp over j, scatter to out[g][:][i] ----
    {
        float vals[8];
        float mx = -1e30f;
        #pragma unroll
        for (int q = 0; q < 8; q++) {
            vals[q] = logits_s[g * 256 + q * 32 + lane];
            mx = fmaxf(mx, vals[q]);
        }
        mx = warp_max(mx);
        float se = 0.0f;
        #pragma unroll
        for (int q = 0; q < 8; q++) se += __expf(vals[q] - mx);
        se = warp_sum(se);
        const float lse = mx + __logf(se);

        float* og = out + (size_t)g * (NIP * NIP);
        #pragma unroll
        for (int q = 0; q < 8; q++)
            og[(size_t)(q * 32 + lane) * NIP + i] = __expf(vals[q] - lse);
    }
}

// ---------------------------------------------------------------------------
// Input net (R3 structure, tanh.approx). Block = g, 512 threads.
// ---------------------------------------------------------------------------
__global__ void __launch_bounds__(512) input_kernel(
    const float* __restrict__ z,
    const float* __restrict__ coeff,   // [32]
    const float* __restrict__ w1,      // [784*64][64]
    const float* __restrict__ w2,      // [784][256][64]
    float* __restrict__ out)           // [784][256][256]
{
    float* his    = s_dyn;                 // 64 * PADN floats (tf32 bits)
    float* logits = s_dyn + 64 * PADN;     // 32 * PADC floats (aliases W1s)
    float* W1s    = logits;                // 4096 floats, stage-1 only
    __shared__ float ic[32];

    const int g    = blockIdx.x;
    const int tid  = threadIdx.x;
    const int lane = tid & 31;
    const int warp = tid >> 5;

    if (tid < 32) ic[tid] = coeff[tid];
    for (int t = tid; t < 4096; t += 512) W1s[t] = w1[(size_t)g * 4096 + t];
    __syncthreads();

    // ---- stage 1: thread (n, d-half) ----
    {
        const int n  = tid & 255;
        const int dh = tid >> 8;
        const float zn = z[n];
        float ff[64];
        #pragma unroll
        for (int k = 0; k < 32; k++) {
            float s, c;
            __sincosf(TWO_PI * zn * ic[k], &s, &c);
            ff[k]      = c;
            ff[32 + k] = s;
        }
        uint32_t* hisU = (uint32_t*)his;
        #pragma unroll 4
        for (int d = dh * 32; d < dh * 32 + 32; d++) {
            const float4* wrow = (const float4*)&W1s[d * 64];
            float s0 = 0.f, s1 = 0.f, s2 = 0.f, s3 = 0.f;
            #pragma unroll
            for (int t = 0; t < 16; t++) {
                float4 a = wrow[t];
                s0 = fmaf(a.x, ff[t * 4 + 0], s0);
                s1 = fmaf(a.y, ff[t * 4 + 1], s1);
                s2 = fmaf(a.z, ff[t * 4 + 2], s2);
                s3 = fmaf(a.w, ff[t * 4 + 3], s3);
            }
            float hv = tanha((s0 + s1) + (s2 + s3));
            hisU[d * PADN + n] = f2tf32(hv);
        }
    }
    __syncthreads();   // his complete; W1s region now free for logits

    // ---- stage 2 ----
    const int gq = lane >> 2;
    const int T  = lane & 3;
    const int cbase = warp * 16;

    uint32_t A[8][4];
    {
        const float* w2g = w2 + (size_t)g * 256 * 64;
        #pragma unroll
        for (int kk = 0; kk < 8; kk++) {
            A[kk][0] = f2tf32(w2g[(cbase + gq)     * 64 + kk * 8 + T]);
            A[kk][1] = f2tf32(w2g[(cbase + 8 + gq) * 64 + kk * 8 + T]);
            A[kk][2] = f2tf32(w2g[(cbase + gq)     * 64 + kk * 8 + T + 4]);
            A[kk][3] = f2tf32(w2g[(cbase + 8 + gq) * 64 + kk * 8 + T + 4]);
        }
    }

    const uint32_t* hisU = (const uint32_t*)his;
    float* outg = out + (size_t)g * (NIP * N_CAT);

    for (int pass = 0; pass < 8; pass++) {
        const int n0 = pass * 32;

        float acc[4][4];
        #pragma unroll
        for (int nt = 0; nt < 4; nt++)
            #pragma unroll
            for (int u = 0; u < 4; u++) acc[nt][u] = 0.0f;

        #pragma unroll
        for (int kk = 0; kk < 8; kk++) {
            uint32_t B0[4], B1[4];
            #pragma unroll
            for (int nt = 0; nt < 4; nt++) {
                const int ncol = n0 + nt * 8 + gq;
                B0[nt] = hisU[(kk * 8 + T)     * PADN + ncol];
                B1[nt] = hisU[(kk * 8 + T + 4) * PADN + ncol];
            }
            #pragma unroll
            for (int nt = 0; nt < 4; nt++)
                mma_tf32(acc[nt], A[kk], B0[nt], B1[nt]);
        }

        #pragma unroll
        for (int nt = 0; nt < 4; nt++) {
            const int nl = nt * 8 + 2 * T;
            logits[nl       * PADC + cbase + gq]     = acc[nt][0];
            logits[(nl + 1) * PADC + cbase + gq]     = acc[nt][1];
            logits[nl       * PADC + cbase + 8 + gq] = acc[nt][2];
            logits[(nl + 1) * PADC + cbase + 8 + gq] = acc[nt][3];
        }
        __syncthreads();

        {
            const int nl  = tid >> 4;
            const int sub = tid & 15;
            const float* row = logits + nl * PADC;

            float4 v[4];
            float mx = -1e30f;
            #pragma unroll
            for (int q = 0; q < 4; q++) {
                v[q] = *(const float4*)(row + q * 64 + sub * 4);
                mx = fmaxf(mx, fmaxf(fmaxf(v[q].x, v[q].y), fmaxf(v[q].z, v[q].w)));
            }
            #pragma unroll
            for (int o = 1; o < 16; o <<= 1)
                mx = fmaxf(mx, __shfl_xor_sync(0xffffffffu, mx, o));

            float se = 0.0f;
            #pragma unroll
            for (int q = 0; q < 4; q++) {
                se += __expf(v[q].x - mx) + __expf(v[q].y - mx)
                    + __expf(v[q].z - mx) + __expf(v[q].w - mx);
            }
            #pragma unroll
            for (int o = 1; o < 16; o <<= 1)
                se += __shfl_xor_sync(0xffffffffu, se, o);

            const float lse = mx + __logf(se);
            float* orow = outg + (size_t)(n0 + nl) * N_CAT;
            #pragma unroll
            for (int q = 0; q < 4; q++) {
                float4 o4;
                o4.x = v[q].x - lse; o4.y = v[q].y - lse;
                o4.z = v[q].z - lse; o4.w = v[q].w - lse;
                *(float4*)(orow + q * 64 + sub * 4) = o4;
            }
        }
        __syncthreads();
    }
}

// ---------------------------------------------------------------------------
// launch
// ---------------------------------------------------------------------------
extern "C" void kernel_launch(void* const* d_in, const int* in_sizes, int n_in,
                              void* d_out, int out_size) {
    (void)in_sizes; (void)n_in; (void)out_size;
    const float* z           = (const float*)d_in[0];
    const float* log_w       = (const float*)d_in[1];
    const float* inner_coeff = (const float*)d_in[2];
    const float* inner_w1    = (const float*)d_in[3];
    const float* inner_w2    = (const float*)d_in[4];
    const float* input_coeff = (const float*)d_in[5];
    const float* input_w1    = (const float*)d_in[6];
    const float* input_w2    = (const float*)d_in[7];
    float* out = (float*)d_out;

    const int smem_inner = (64 * PADN + 16 * 256 + 256 + 64) * (int)sizeof(float);
    const int smem_input = (64 * PADN + 32 * PADC) * (int)sizeof(float);
    cudaFuncSetAttribute(inner_kernel,
                         cudaFuncAttributeMaxDynamicSharedMemorySize, smem_inner);
    cudaFuncSetAttribute(input_kernel,
                         cudaFuncAttributeMaxDynamicSharedMemorySize, smem_input);

    inner_kernel<<<NIP, 512, smem_inner>>>(z, log_w, inner_coeff, inner_w1,
                                           inner_w2, out);
    input_kernel<<<N_INPUT, 512, smem_input>>>(z, input_coeff, input_w1, input_w2,
                                               out + (size_t)N_INNER * NIP * NIP);
}

// round 5
// speedup vs baseline: 3.4916x; 1.3586x over previous
#include <cuda_runtime.h>
#include <cuda_bf16.h>
#include <math.h>
#include <stdint.h>

#define NIP       256
#define N_INNER   16
#define NET_DIM   64
#define N_INPUT   784
#define N_CAT     256
#define TWO_PI    6.283185307179586f

#define PADN 264   // tf32 tile row pitch (words): 264%32==8 -> banks 8T+gq distinct
#define PADC 260   // logits row pitch (words)
#define PH   36    // his row pitch in 32-bit words (72 halfs): 36%32==4 -> 4gq+T distinct

// ---------------------------------------------------------------------------
// helpers
// ---------------------------------------------------------------------------
__device__ __forceinline__ float tanha(float x) {
    float y;
    asm("tanh.approx.f32 %0, %1;" : "=f"(y) : "f"(x));
    return y;
}

__device__ __forceinline__ float softplus_f(float x) {
    float ax = fabsf(x);
    return fmaxf(x, 0.0f) + log1pf(__expf(-ax));
}

__device__ __forceinline__ float warp_max(float v) {
    #pragma unroll
    for (int o = 16; o > 0; o >>= 1)
        v = fmaxf(v, __shfl_xor_sync(0xffffffffu, v, o));
    return v;
}

__device__ __forceinline__ float warp_sum(float v) {
    #pragma unroll
    for (int o = 16; o > 0; o >>= 1)
        v += __shfl_xor_sync(0xffffffffu, v, o);
    return v;
}

__device__ __forceinline__ uint32_t f2tf32(float x) {
    uint32_t u;
    asm("cvt.rna.tf32.f32 %0, %1;" : "=r"(u) : "f"(x));
    return u;
}

__device__ __forceinline__ uint32_t pack_bf16(float lo, float hi) {
    __nv_bfloat162 h = __floats2bfloat162_rn(lo, hi);
    return *(uint32_t*)&h;
}

// D += A(16x8,row) * B(8x8,col), tf32
__device__ __forceinline__ void mma_tf32(float* c, const uint32_t* a,
                                         uint32_t b0, uint32_t b1) {
    asm volatile(
        "mma.sync.aligned.m16n8k8.row.col.f32.tf32.tf32.f32 "
        "{%0,%1,%2,%3}, {%4,%5,%6,%7}, {%8,%9}, {%0,%1,%2,%3};"
        : "+f"(c[0]), "+f"(c[1]), "+f"(c[2]), "+f"(c[3])
        : "r"(a[0]), "r"(a[1]), "r"(a[2]), "r"(a[3]), "r"(b0), "r"(b1));
}

// D += A(16x16,row) * B(16x8,col), bf16
__device__ __forceinline__ void mma_bf16(float* c, const uint32_t* a,
                                         uint32_t b0, uint32_t b1) {
    asm volatile(
        "mma.sync.aligned.m16n8k16.row.col.f32.bf16.bf16.f32 "
        "{%0,%1,%2,%3}, {%4,%5,%6,%7}, {%8,%9}, {%0,%1,%2,%3};"
        : "+f"(c[0]), "+f"(c[1]), "+f"(c[2]), "+f"(c[3])
        : "r"(a[0]), "r"(a[1]), "r"(a[2]), "r"(a[3]), "r"(b0), "r"(b1));
}

extern __shared__ float s_dyn[];

// ---------------------------------------------------------------------------
// Inner net (unchanged from R4). Block = i (256), 512 threads, warp = g.
// ---------------------------------------------------------------------------
__global__ void __launch_bounds__(512, 1) inner_kernel(
    const float* __restrict__ z, const float* __restrict__ log_w,
    const float* __restrict__ coeff,   // [2][32]
    const float* __restrict__ w1,      // [1024][64]
    const float* __restrict__ w2,      // [16][64]
    float* __restrict__ out)           // [16][256][256]
{
    uint32_t* fftU     = (uint32_t*)s_dyn;            // 64 * PADN
    float*    logits_s = s_dyn + 64 * PADN;           // 16 * 256
    float*    logw_s   = logits_s + 16 * 256;         // 256
    float*    cc       = logw_s + 256;                // 64

    const int i    = blockIdx.x;
    const int tid  = threadIdx.x;
    const int lane = tid & 31;
    const int warp = tid >> 5;

    if (tid < 64) cc[tid] = coeff[tid];
    if (tid < 256) logw_s[tid] = log_w[tid];
    __syncthreads();

    {
        const int j  = tid & 255;
        const int kh = tid >> 8;
        const float zi = z[i];
        const float zj = z[j];
        #pragma unroll
        for (int k = kh * 16; k < kh * 16 + 16; k++) {
            float ang = TWO_PI * fmaf(zi, cc[k], zj * cc[32 + k]);
            float s, c;
            __sincosf(ang, &s, &c);
            fftU[k * PADN + j]        = f2tf32(c);
            fftU[(k + 32) * PADN + j] = f2tf32(s);
        }
    }
    __syncthreads();

    const int g  = warp;
    const int gq = lane >> 2;
    const int T  = lane & 3;
    const float* w1g = w1 + g * (NET_DIM * NET_DIM);
    const float* w2g = w2 + g * NET_DIM;

    for (int h = 0; h < 2; h++) {
        float plog[32];
        #pragma unroll
        for (int e = 0; e < 32; e++) plog[e] = 0.0f;

        for (int mt = 0; mt < 4; mt++) {
            uint32_t A[8][4];
            const int r0 = mt * 16 + gq;
            const int r1 = mt * 16 + 8 + gq;
            #pragma unroll
            for (int kk = 0; kk < 8; kk++) {
                A[kk][0] = f2tf32(w1g[r0 * 64 + kk * 8 + T]);
                A[kk][1] = f2tf32(w1g[r1 * 64 + kk * 8 + T]);
                A[kk][2] = f2tf32(w1g[r0 * 64 + kk * 8 + T + 4]);
                A[kk][3] = f2tf32(w1g[r1 * 64 + kk * 8 + T + 4]);
            }
            const float w2a = w2g[mt * 16 + gq];
            const float w2b = w2g[mt * 16 + 8 + gq];

            #pragma unroll
            for (int ntp = 0; ntp < 8; ntp++) {
                const int j0 = (h * 16 + ntp * 2) * 8;
                float acc0[4] = {0.f, 0.f, 0.f, 0.f};
                float acc1[4] = {0.f, 0.f, 0.f, 0.f};
                #pragma unroll
                for (int kk = 0; kk < 8; kk++) {
                    uint32_t B0a = fftU[(kk * 8 + T)     * PADN + j0 + gq];
                    uint32_t B1a = fftU[(kk * 8 + T + 4) * PADN + j0 + gq];
                    uint32_t B0b = fftU[(kk * 8 + T)     * PADN + j0 + 8 + gq];
                    uint32_t B1b = fftU[(kk * 8 + T + 4) * PADN + j0 + 8 + gq];
                    mma_tf32(acc0, A[kk], B0a, B1a);
                    mma_tf32(acc1, A[kk], B0b, B1b);
                }
                plog[ntp * 4 + 0] += w2a * tanha(acc0[0]) + w2b * tanha(acc0[2]);
                plog[ntp * 4 + 1] += w2a * tanha(acc0[1]) + w2b * tanha(acc0[3]);
                plog[ntp * 4 + 2] += w2a * tanha(acc1[0]) + w2b * tanha(acc1[2]);
                plog[ntp * 4 + 3] += w2a * tanha(acc1[1]) + w2b * tanha(acc1[3]);
            }
        }

        #pragma unroll
        for (int e = 0; e < 32; e++) {
            float v = plog[e];
            v += __shfl_xor_sync(0xffffffffu, v, 4);
            v += __shfl_xor_sync(0xffffffffu, v, 8);
            v += __shfl_xor_sync(0xffffffffu, v, 16);
            if (lane < 4) {
                const int j = (h * 16 + (e >> 1)) * 8 + 2 * T + (e & 1);
                logits_s[g * 256 + j] = -softplus_f(v) + logw_s[j];
            }
        }
    }
    __syncwarp();

    {
        float vals[8];
        float mx = -1e30f;
        #pragma unroll
        for (int q = 0; q < 8; q++) {
            vals[q] = logits_s[g * 256 + q * 32 + lane];
            mx = fmaxf(mx, vals[q]);
        }
        mx = warp_max(mx);
        float se = 0.0f;
        #pragma unroll
        for (int q = 0; q < 8; q++) se += __expf(vals[q] - mx);
        se = warp_sum(se);
        const float lse = mx + __logf(se);

        float* og = out + (size_t)g * (NIP * NIP);
        #pragma unroll
        for (int q = 0; q < 8; q++)
            og[(size_t)(q * 32 + lane) * NIP + i] = __expf(vals[q] - lse);
    }
}

// ---------------------------------------------------------------------------
// Input net v2, all-mma. Block = g, 512 threads, 2 blocks/SM.
// smem: ffU (64*PADN tf32, aliased by logits 32*PADC after stage 1)
//       hisw (256 rows * PH words, bf16x2 packed over d)
// Stage 1 (tf32 mma): H = tanh(W1_g @ ff)  -> his[n][d] bf16
// Stage 2 (bf16 mma): logits[n][c] = H^T @ W2_g^T, W2 register-resident
// ---------------------------------------------------------------------------
__global__ void __launch_bounds__(512, 2) input_kernel(
    const float* __restrict__ z,
    const float* __restrict__ coeff,   // [32]
    const float* __restrict__ w1,      // [784*64][64]
    const float* __restrict__ w2,      // [784][256][64]
    float* __restrict__ out)           // [784][256][256]
{
    uint32_t* ffU    = (uint32_t*)s_dyn;               // 64*PADN words
    float*    logits = s_dyn;                          // 32*PADC, alias of ffU
    uint32_t* hisw   = (uint32_t*)(s_dyn + 64 * PADN); // 256*PH words
    __shared__ float ic[32];

    const int g    = blockIdx.x;
    const int tid  = threadIdx.x;
    const int lane = tid & 31;
    const int warp = tid >> 5;
    const int gq   = lane >> 2;
    const int T    = lane & 3;

    if (tid < 32) ic[tid] = coeff[tid];
    __syncthreads();

    // ---- phase 0: fourier features (tf32, transposed) ----
    {
        const int n  = tid & 255;
        const int kh = tid >> 8;
        const float zn = z[n];
        #pragma unroll
        for (int k = kh * 16; k < kh * 16 + 16; k++) {
            float s, c;
            __sincosf(TWO_PI * zn * ic[k], &s, &c);
            ffU[k * PADN + n]        = f2tf32(c);
            ffU[(k + 32) * PADN + n] = f2tf32(s);
        }
    }
    __syncthreads();

    // ---- stage 1: H via tf32 mma, write bf16 his[n][d] ----
    {
        const int mt = warp & 3;        // d tile of 16
        const int nb = warp >> 2;       // n block of 64
        const float* w1g = w1 + (size_t)g * 4096;

        uint32_t A1[8][4];
        const int r0 = (mt * 16 + gq) * 64;
        const int r1 = (mt * 16 + 8 + gq) * 64;
        #pragma unroll
        for (int kk = 0; kk < 8; kk++) {
            A1[kk][0] = f2tf32(w1g[r0 + kk * 8 + T]);
            A1[kk][1] = f2tf32(w1g[r1 + kk * 8 + T]);
            A1[kk][2] = f2tf32(w1g[r0 + kk * 8 + T + 4]);
            A1[kk][3] = f2tf32(w1g[r1 + kk * 8 + T + 4]);
        }

        __nv_bfloat16* hish = (__nv_bfloat16*)hisw;
        const int d0 = mt * 16 + gq;

        #pragma unroll
        for (int t = 0; t < 8; t++) {
            const int n0 = nb * 64 + t * 8;
            float acc[4] = {0.f, 0.f, 0.f, 0.f};
            #pragma unroll
            for (int kk = 0; kk < 8; kk++) {
                uint32_t b0 = ffU[(kk * 8 + T)     * PADN + n0 + gq];
                uint32_t b1 = ffU[(kk * 8 + T + 4) * PADN + n0 + gq];
                mma_tf32(acc, A1[kk], b0, b1);
            }
            const int na = n0 + 2 * T;
            hish[na       * (2 * PH) + d0]     = __float2bfloat16_rn(tanha(acc[0]));
            hish[(na + 1) * (2 * PH) + d0]     = __float2bfloat16_rn(tanha(acc[1]));
            hish[na       * (2 * PH) + d0 + 8] = __float2bfloat16_rn(tanha(acc[2]));
            hish[(na + 1) * (2 * PH) + d0 + 8] = __float2bfloat16_rn(tanha(acc[3]));
        }
    }
    __syncthreads();   // his done; ffU region free -> logits

    // ---- stage 2: logits[n][c] via bf16 mma, W2 in registers ----
    const int cb = warp * 16;    // c range [cb, cb+16): 2 c-tiles of 8
    uint32_t Bw[2][4][2];
    {
        const float* w2g = w2 + (size_t)g * 256 * 64;
        #pragma unroll
        for (int ct = 0; ct < 2; ct++) {
            const float* w2c = w2g + (cb + ct * 8 + gq) * 64;
            #pragma unroll
            for (int kk = 0; kk < 4; kk++) {
                Bw[ct][kk][0] = pack_bf16(w2c[kk * 16 + 2 * T],     w2c[kk * 16 + 2 * T + 1]);
                Bw[ct][kk][1] = pack_bf16(w2c[kk * 16 + 2 * T + 8], w2c[kk * 16 + 2 * T + 9]);
            }
        }
    }

    float* outg = out + (size_t)g * (NIP * N_CAT);

    for (int pass = 0; pass < 8; pass++) {
        const int n0 = pass * 32;

        #pragma unroll
        for (int mt2 = 0; mt2 < 2; mt2++) {
            const int m0 = n0 + mt2 * 16;
            uint32_t A2[4][4];
            #pragma unroll
            for (int kk = 0; kk < 4; kk++) {
                A2[kk][0] = hisw[(m0 + gq)     * PH + kk * 8 + T];
                A2[kk][1] = hisw[(m0 + 8 + gq) * PH + kk * 8 + T];
                A2[kk][2] = hisw[(m0 + gq)     * PH + kk * 8 + T + 4];
                A2[kk][3] = hisw[(m0 + 8 + gq) * PH + kk * 8 + T + 4];
            }
            #pragma unroll
            for (int ct = 0; ct < 2; ct++) {
                float acc[4] = {0.f, 0.f, 0.f, 0.f};
                #pragma unroll
                for (int kk = 0; kk < 4; kk++)
                    mma_bf16(acc, A2[kk], Bw[ct][kk][0], Bw[ct][kk][1]);
                const int nl = mt2 * 16 + gq;
                const int cc0 = cb + ct * 8 + 2 * T;
                *(float2*)&logits[nl       * PADC + cc0] = make_float2(acc[0], acc[1]);
                *(float2*)&logits[(nl + 8) * PADC + cc0] = make_float2(acc[2], acc[3]);
            }
        }
        __syncthreads();

        // epilogue: thread -> (nl = tid>>4, sub = tid&15), 32 c per thread
        {
            const int nl  = tid >> 4;
            const int sub = tid & 15;
            const float* row = logits + nl * PADC;

            float4 v[4];
            float mx = -1e30f;
            #pragma unroll
            for (int q = 0; q < 4; q++) {
                v[q] = *(const float4*)(row + q * 64 + sub * 4);
                mx = fmaxf(mx, fmaxf(fmaxf(v[q].x, v[q].y), fmaxf(v[q].z, v[q].w)));
            }
            #pragma unroll
            for (int o = 1; o < 16; o <<= 1)
                mx = fmaxf(mx, __shfl_xor_sync(0xffffffffu, mx, o));

            float se = 0.0f;
            #pragma unroll
            for (int q = 0; q < 4; q++) {
                se += __expf(v[q].x - mx) + __expf(v[q].y - mx)
                    + __expf(v[q].z - mx) + __expf(v[q].w - mx);
            }
            #pragma unroll
            for (int o = 1; o < 16; o <<= 1)
                se += __shfl_xor_sync(0xffffffffu, se, o);

            const float lse = mx + __logf(se);
            float* orow = outg + (size_t)(n0 + nl) * N_CAT;
            #pragma unroll
            for (int q = 0; q < 4; q++) {
                float4 o4;
                o4.x = v[q].x - lse; o4.y = v[q].y - lse;
                o4.z = v[q].z - lse; o4.w = v[q].w - lse;
                *(float4*)(orow + q * 64 + sub * 4) = o4;
            }
        }
        __syncthreads();
    }
}

// ---------------------------------------------------------------------------
// launch
// ---------------------------------------------------------------------------
extern "C" void kernel_launch(void* const* d_in, const int* in_sizes, int n_in,
                              void* d_out, int out_size) {
    (void)in_sizes; (void)n_in; (void)out_size;
    const float* z           = (const float*)d_in[0];
    const float* log_w       = (const float*)d_in[1];
    const float* inner_coeff = (const float*)d_in[2];
    const float* inner_w1    = (const float*)d_in[3];
    const float* inner_w2    = (const float*)d_in[4];
    const float* input_coeff = (const float*)d_in[5];
    const float* input_w1    = (const float*)d_in[6];
    const float* input_w2    = (const float*)d_in[7];
    float* out = (float*)d_out;

    const int smem_inner = (64 * PADN + 16 * 256 + 256 + 64) * (int)sizeof(float);
    const int smem_input = (64 * PADN + 256 * PH) * (int)sizeof(float);
    cudaFuncSetAttribute(inner_kernel,
                         cudaFuncAttributeMaxDynamicSharedMemorySize, smem_inner);
    cudaFuncSetAttribute(input_kernel,
                         cudaFuncAttributeMaxDynamicSharedMemorySize, smem_input);

    inner_kernel<<<NIP, 512, smem_inner>>>(z, log_w, inner_coeff, inner_w1,
                                           inner_w2, out);
    input_kernel<<<N_INPUT, 512, smem_input>>>(z, input_coeff, input_w1, input_w2,
                                               out + (size_t)N_INNER * NIP * NIP);
}

// round 6
// speedup vs baseline: 3.6027x; 1.0318x over previous
#include <cuda_runtime.h>
#include <cuda_bf16.h>
#include <math.h>
#include <stdint.h>

#define NIP       256
#define N_INNER   16
#define NET_DIM   64
#define N_INPUT   784
#define N_CAT     256
#define TWO_PI    6.283185307179586f

#define PADN 264   // tf32 tile row pitch (words): 264%32==8 -> banks 8T+gq distinct
#define PADC 260   // logits row pitch (words)
#define PH   36    // his row pitch in 32-bit words (72 halfs)

// ---------------------------------------------------------------------------
// helpers
// ---------------------------------------------------------------------------
__device__ __forceinline__ float tanha(float x) {
    float y;
    asm("tanh.approx.f32 %0, %1;" : "=f"(y) : "f"(x));
    return y;
}

__device__ __forceinline__ float softplus_f(float x) {
    float ax = fabsf(x);
    return fmaxf(x, 0.0f) + log1pf(__expf(-ax));
}

__device__ __forceinline__ float warp_max(float v) {
    #pragma unroll
    for (int o = 16; o > 0; o >>= 1)
        v = fmaxf(v, __shfl_xor_sync(0xffffffffu, v, o));
    return v;
}

__device__ __forceinline__ float warp_sum(float v) {
    #pragma unroll
    for (int o = 16; o > 0; o >>= 1)
        v += __shfl_xor_sync(0xffffffffu, v, o);
    return v;
}

__device__ __forceinline__ uint32_t f2tf32(float x) {
    uint32_t u;
    asm("cvt.rna.tf32.f32 %0, %1;" : "=r"(u) : "f"(x));
    return u;
}

__device__ __forceinline__ uint32_t pack_bf16(float lo, float hi) {
    __nv_bfloat162 h = __floats2bfloat162_rn(lo, hi);
    return *(uint32_t*)&h;
}

__device__ __forceinline__ void mma_tf32(float* c, const uint32_t* a,
                                         uint32_t b0, uint32_t b1) {
    asm volatile(
        "mma.sync.aligned.m16n8k8.row.col.f32.tf32.tf32.f32 "
        "{%0,%1,%2,%3}, {%4,%5,%6,%7}, {%8,%9}, {%0,%1,%2,%3};"
        : "+f"(c[0]), "+f"(c[1]), "+f"(c[2]), "+f"(c[3])
        : "r"(a[0]), "r"(a[1]), "r"(a[2]), "r"(a[3]), "r"(b0), "r"(b1));
}

__device__ __forceinline__ void mma_bf16(float* c, const uint32_t* a,
                                         uint32_t b0, uint32_t b1) {
    asm volatile(
        "mma.sync.aligned.m16n8k16.row.col.f32.bf16.bf16.f32 "
        "{%0,%1,%2,%3}, {%4,%5,%6,%7}, {%8,%9}, {%0,%1,%2,%3};"
        : "+f"(c[0]), "+f"(c[1]), "+f"(c[2]), "+f"(c[3])
        : "r"(a[0]), "r"(a[1]), "r"(a[2]), "r"(a[3]), "r"(b0), "r"(b1));
}

extern __shared__ float s_dyn[];

// ---------------------------------------------------------------------------
// Inner-net path. Block = i, 512 threads, warp = g.
// j processed in quarters of 64 to keep plog[] at 16 regs.
// ---------------------------------------------------------------------------
__device__ void inner_path(
    int i,
    const float* __restrict__ z, const float* __restrict__ log_w,
    const float* __restrict__ coeff,
    const float* __restrict__ w1,
    const float* __restrict__ w2,
    float* __restrict__ out)
{
    uint32_t* fftU     = (uint32_t*)s_dyn;            // 64 * PADN
    float*    logits_s = s_dyn + 64 * PADN;           // 16 * 256
    float*    logw_s   = logits_s + 16 * 256;         // 256
    float*    cc       = logw_s + 256;                // 64

    const int tid  = threadIdx.x;
    const int lane = tid & 31;
    const int warp = tid >> 5;

    if (tid < 64) cc[tid] = coeff[tid];
    if (tid < 256) logw_s[tid] = log_w[tid];
    __syncthreads();

    {
        const int j  = tid & 255;
        const int kh = tid >> 8;
        const float zi = z[i];
        const float zj = z[j];
        #pragma unroll
        for (int k = kh * 16; k < kh * 16 + 16; k++) {
            float ang = TWO_PI * fmaf(zi, cc[k], zj * cc[32 + k]);
            float s, c;
            __sincosf(ang, &s, &c);
            fftU[k * PADN + j]        = f2tf32(c);
            fftU[(k + 32) * PADN + j] = f2tf32(s);
        }
    }
    __syncthreads();

    const int g  = warp;
    const int gq = lane >> 2;
    const int T  = lane & 3;
    const float* w1g = w1 + g * (NET_DIM * NET_DIM);
    const float* w2g = w2 + g * NET_DIM;

    for (int h = 0; h < 4; h++) {          // j quarters of 64
        float plog[16];
        #pragma unroll
        for (int e = 0; e < 16; e++) plog[e] = 0.0f;

        for (int mt = 0; mt < 4; mt++) {   // d tiles of 16
            uint32_t A[8][4];
            const int r0 = (mt * 16 + gq) * 64;
            const int r1 = (mt * 16 + 8 + gq) * 64;
            #pragma unroll
            for (int kk = 0; kk < 8; kk++) {
                A[kk][0] = f2tf32(w1g[r0 + kk * 8 + T]);
                A[kk][1] = f2tf32(w1g[r1 + kk * 8 + T]);
                A[kk][2] = f2tf32(w1g[r0 + kk * 8 + T + 4]);
                A[kk][3] = f2tf32(w1g[r1 + kk * 8 + T + 4]);
            }
            const float w2a = w2g[mt * 16 + gq];
            const float w2b = w2g[mt * 16 + 8 + gq];

            #pragma unroll
            for (int ntp = 0; ntp < 4; ntp++) {   // 2 n-tiles (16 j) per iter
                const int j0 = (h * 8 + ntp * 2) * 8;
                float acc0[4] = {0.f, 0.f, 0.f, 0.f};
                float acc1[4] = {0.f, 0.f, 0.f, 0.f};
                #pragma unroll
                for (int kk = 0; kk < 8; kk++) {
                    uint32_t B0a = fftU[(kk * 8 + T)     * PADN + j0 + gq];
                    uint32_t B1a = fftU[(kk * 8 + T + 4) * PADN + j0 + gq];
                    uint32_t B0b = fftU[(kk * 8 + T)     * PADN + j0 + 8 + gq];
                    uint32_t B1b = fftU[(kk * 8 + T + 4) * PADN + j0 + 8 + gq];
                    mma_tf32(acc0, A[kk], B0a, B1a);
                    mma_tf32(acc1, A[kk], B0b, B1b);
                }
                plog[ntp * 4 + 0] += w2a * tanha(acc0[0]) + w2b * tanha(acc0[2]);
                plog[ntp * 4 + 1] += w2a * tanha(acc0[1]) + w2b * tanha(acc0[3]);
                plog[ntp * 4 + 2] += w2a * tanha(acc1[0]) + w2b * tanha(acc1[2]);
                plog[ntp * 4 + 3] += w2a * tanha(acc1[1]) + w2b * tanha(acc1[3]);
            }
        }

        #pragma unroll
        for (int e = 0; e < 16; e++) {
            float v = plog[e];
            v += __shfl_xor_sync(0xffffffffu, v, 4);
            v += __shfl_xor_sync(0xffffffffu, v, 8);
            v += __shfl_xor_sync(0xffffffffu, v, 16);
            if (lane < 4) {
                const int j = (h * 8 + (e >> 1)) * 8 + 2 * T + (e & 1);
                logits_s[g * 256 + j] = -softplus_f(v) + logw_s[j];
            }
        }
    }
    __syncwarp();

    {
        float vals[8];
        float mx = -1e30f;
        #pragma unroll
        for (int q = 0; q < 8; q++) {
            vals[q] = logits_s[g * 256 + q * 32 + lane];
            mx = fmaxf(mx, vals[q]);
        }
        mx = warp_max(mx);
        float se = 0.0f;
        #pragma unroll
        for (int q = 0; q < 8; q++) se += __expf(vals[q] - mx);
        se = warp_sum(se);
        const float lse = mx + __logf(se);

        float* og = out + (size_t)g * (NIP * NIP);
        #pragma unroll
        for (int q = 0; q < 8; q++)
            og[(size_t)(q * 32 + lane) * NIP + i] = __expf(vals[q] - lse);
    }
}

// ---------------------------------------------------------------------------
// Input-net path (R5 structure). Block = g, 512 threads.
// ---------------------------------------------------------------------------
__device__ void input_path(
    int g,
    const float* __restrict__ z,
    const float* __restrict__ coeff,
    const float* __restrict__ w1,
    const float* __restrict__ w2,
    float* __restrict__ out)
{
    uint32_t* ffU    = (uint32_t*)s_dyn;               // 64*PADN words
    float*    logits = s_dyn;                          // 32*PADC, alias of ffU
    uint32_t* hisw   = (uint32_t*)(s_dyn + 64 * PADN); // 256*PH words
    float*    ic     = s_dyn + 64 * PADN + 256 * PH;   // 32

    const int tid  = threadIdx.x;
    const int lane = tid & 31;
    const int warp = tid >> 5;
    const int gq   = lane >> 2;
    const int T    = lane & 3;

    if (tid < 32) ic[tid] = coeff[tid];
    __syncthreads();

    // ---- phase 0: fourier features (tf32, transposed) ----
    {
        const int n  = tid & 255;
        const int kh = tid >> 8;
        const float zn = z[n];
        #pragma unroll
        for (int k = kh * 16; k < kh * 16 + 16; k++) {
            float s, c;
            __sincosf(TWO_PI * zn * ic[k], &s, &c);
            ffU[k * PADN + n]        = f2tf32(c);
            ffU[(k + 32) * PADN + n] = f2tf32(s);
        }
    }
    __syncthreads();

    // ---- stage 1: H via tf32 mma, write bf16 his[n][d] ----
    {
        const int mt = warp & 3;
        const int nb = warp >> 2;
        const float* w1g = w1 + (size_t)g * 4096;

        uint32_t A1[8][4];
        const int r0 = (mt * 16 + gq) * 64;
        const int r1 = (mt * 16 + 8 + gq) * 64;
        #pragma unroll
        for (int kk = 0; kk < 8; kk++) {
            A1[kk][0] = f2tf32(w1g[r0 + kk * 8 + T]);
            A1[kk][1] = f2tf32(w1g[r1 + kk * 8 + T]);
            A1[kk][2] = f2tf32(w1g[r0 + kk * 8 + T + 4]);
            A1[kk][3] = f2tf32(w1g[r1 + kk * 8 + T + 4]);
        }

        __nv_bfloat16* hish = (__nv_bfloat16*)hisw;
        const int d0 = mt * 16 + gq;

        #pragma unroll
        for (int t = 0; t < 8; t++) {
            const int n0 = nb * 64 + t * 8;
            float acc[4] = {0.f, 0.f, 0.f, 0.f};
            #pragma unroll
            for (int kk = 0; kk < 8; kk++) {
                uint32_t b0 = ffU[(kk * 8 + T)     * PADN + n0 + gq];
                uint32_t b1 = ffU[(kk * 8 + T + 4) * PADN + n0 + gq];
                mma_tf32(acc, A1[kk], b0, b1);
            }
            const int na = n0 + 2 * T;
            hish[na       * (2 * PH) + d0]     = __float2bfloat16_rn(tanha(acc[0]));
            hish[(na + 1) * (2 * PH) + d0]     = __float2bfloat16_rn(tanha(acc[1]));
            hish[na       * (2 * PH) + d0 + 8] = __float2bfloat16_rn(tanha(acc[2]));
            hish[(na + 1) * (2 * PH) + d0 + 8] = __float2bfloat16_rn(tanha(acc[3]));
        }
    }
    __syncthreads();   // his done; ffU region free -> logits

    // ---- stage 2: logits[n][c] via bf16 mma, W2 in registers ----
    const int cb = warp * 16;
    uint32_t Bw[2][4][2];
    {
        const float* w2g = w2 + (size_t)g * 256 * 64;
        #pragma unroll
        for (int ct = 0; ct < 2; ct++) {
            const float* w2c = w2g + (cb + ct * 8 + gq) * 64;
            #pragma unroll
            for (int kk = 0; kk < 4; kk++) {
                Bw[ct][kk][0] = pack_bf16(w2c[kk * 16 + 2 * T],     w2c[kk * 16 + 2 * T + 1]);
                Bw[ct][kk][1] = pack_bf16(w2c[kk * 16 + 2 * T + 8], w2c[kk * 16 + 2 * T + 9]);
            }
        }
    }

    float* outg = out + (size_t)g * (NIP * N_CAT);

    for (int pass = 0; pass < 8; pass++) {
        const int n0 = pass * 32;

        #pragma unroll
        for (int mt2 = 0; mt2 < 2; mt2++) {
            const int m0 = n0 + mt2 * 16;
            uint32_t A2[4][4];
            #pragma unroll
            for (int kk = 0; kk < 4; kk++) {
                A2[kk][0] = hisw[(m0 + gq)     * PH + kk * 8 + T];
                A2[kk][1] = hisw[(m0 + 8 + gq) * PH + kk * 8 + T];
                A2[kk][2] = hisw[(m0 + gq)     * PH + kk * 8 + T + 4];
                A2[kk][3] = hisw[(m0 + 8 + gq) * PH + kk * 8 + T + 4];
            }
            #pragma unroll
            for (int ct = 0; ct < 2; ct++) {
                float acc[4] = {0.f, 0.f, 0.f, 0.f};
                #pragma unroll
                for (int kk = 0; kk < 4; kk++)
                    mma_bf16(acc, A2[kk], Bw[ct][kk][0], Bw[ct][kk][1]);
                const int nl = mt2 * 16 + gq;
                const int cc0 = cb + ct * 8 + 2 * T;
                *(float2*)&logits[nl       * PADC + cc0] = make_float2(acc[0], acc[1]);
                *(float2*)&logits[(nl + 8) * PADC + cc0] = make_float2(acc[2], acc[3]);
            }
        }
        __syncthreads();

        {
            const int nl  = tid >> 4;
            const int sub = tid & 15;
            const float* row = logits + nl * PADC;

            float4 v[4];
            float mx = -1e30f;
            #pragma unroll
            for (int q = 0; q < 4; q++) {
                v[q] = *(const float4*)(row + q * 64 + sub * 4);
                mx = fmaxf(mx, fmaxf(fmaxf(v[q].x, v[q].y), fmaxf(v[q].z, v[q].w)));
            }
            #pragma unroll
            for (int o = 1; o < 16; o <<= 1)
                mx = fmaxf(mx, __shfl_xor_sync(0xffffffffu, mx, o));

            float se = 0.0f;
            #pragma unroll
            for (int q = 0; q < 4; q++) {
                se += __expf(v[q].x - mx) + __expf(v[q].y - mx)
                    + __expf(v[q].z - mx) + __expf(v[q].w - mx);
            }
            #pragma unroll
            for (int o = 1; o < 16; o <<= 1)
                se += __shfl_xor_sync(0xffffffffu, se, o);

            const float lse = mx + __logf(se);
            float* orow = outg + (size_t)(n0 + nl) * N_CAT;
            #pragma unroll
            for (int q = 0; q < 4; q++) {
                float4 o4;
                o4.x = v[q].x - lse; o4.y = v[q].y - lse;
                o4.z = v[q].z - lse; o4.w = v[q].w - lse;
                *(float4*)(orow + q * 64 + sub * 4) = o4;
            }
        }
        __syncthreads();
    }
}

// ---------------------------------------------------------------------------
// Fused fat kernel: blocks 0..255 -> inner net (i), 256..1039 -> input net (g)
// ---------------------------------------------------------------------------
__global__ void __launch_bounds__(512, 2) fused_kernel(
    const float* __restrict__ z, const float* __restrict__ log_w,
    const float* __restrict__ inner_coeff,
    const float* __restrict__ inner_w1,
    const float* __restrict__ inner_w2,
    const float* __restrict__ input_coeff,
    const float* __restrict__ input_w1,
    const float* __restrict__ input_w2,
    float* __restrict__ out)
{
    if (blockIdx.x < NIP) {
        inner_path(blockIdx.x, z, log_w, inner_coeff, inner_w1, inner_w2, out);
    } else {
        input_path(blockIdx.x - NIP, z, input_coeff, input_w1, input_w2,
                   out + (size_t)N_INNER * NIP * NIP);
    }
}

// ---------------------------------------------------------------------------
// launch
// ---------------------------------------------------------------------------
extern "C" void kernel_launch(void* const* d_in, const int* in_sizes, int n_in,
                              void* d_out, int out_size) {
    (void)in_sizes; (void)n_in; (void)out_size;
    const float* z           = (const float*)d_in[0];
    const float* log_w       = (const float*)d_in[1];
    const float* inner_coeff = (const float*)d_in[2];
    const float* inner_w1    = (const float*)d_in[3];
    const float* inner_w2    = (const float*)d_in[4];
    const float* input_coeff = (const float*)d_in[5];
    const float* input_w1    = (const float*)d_in[6];
    const float* input_w2    = (const float*)d_in[7];
    float* out = (float*)d_out;

    const int smem_bytes = (64 * PADN + 256 * PH + 32) * (int)sizeof(float);
    cudaFuncSetAttribute(fused_kernel,
                         cudaFuncAttributeMaxDynamicSharedMemorySize, smem_bytes);

    fused_kernel<<<NIP + N_INPUT, 512, smem_bytes>>>(
        z, log_w, inner_coeff, inner_w1, inner_w2,
        input_coeff, input_w1, input_w2, out);
}

// round 7
// speedup vs baseline: 5.1994x; 1.4432x over previous
#include <cuda_runtime.h>
#include <cuda_bf16.h>
#include <cuda_fp16.h>
#include <math.h>
#include <stdint.h>

#define NIP       256
#define N_INNER   16
#define NET_DIM   64
#define N_INPUT   784
#define N_CAT     256
#define TWO_PI    6.283185307179586f

#define PADN 264   // ff half2-word row pitch: 264%32==8 -> banks 8T+gq distinct
#define PADC 260   // logits row pitch (words)
#define PH   36    // his row pitch in 32-bit words (72 halfs)

// ---------------------------------------------------------------------------
// helpers
// ---------------------------------------------------------------------------
__device__ __forceinline__ float tanha(float x) {
    float y;
    asm("tanh.approx.f32 %0, %1;" : "=f"(y) : "f"(x));
    return y;
}

__device__ __forceinline__ float softplus_f(float x) {
    float ax = fabsf(x);
    return fmaxf(x, 0.0f) + log1pf(__expf(-ax));
}

__device__ __forceinline__ float warp_max(float v) {
    #pragma unroll
    for (int o = 16; o > 0; o >>= 1)
        v = fmaxf(v, __shfl_xor_sync(0xffffffffu, v, o));
    return v;
}

__device__ __forceinline__ float warp_sum(float v) {
    #pragma unroll
    for (int o = 16; o > 0; o >>= 1)
        v += __shfl_xor_sync(0xffffffffu, v, o);
    return v;
}

__device__ __forceinline__ uint32_t packh(float a, float b) {
    __half2 h = __floats2half2_rn(a, b);
    return *(uint32_t*)&h;
}

// D += A(16x16,row) * B(16x8,col), fp16 inputs, fp32 accum
__device__ __forceinline__ void mma_f16(float* c, const uint32_t* a,
                                        uint32_t b0, uint32_t b1) {
    asm volatile(
        "mma.sync.aligned.m16n8k16.row.col.f32.f16.f16.f32 "
        "{%0,%1,%2,%3}, {%4,%5,%6,%7}, {%8,%9}, {%0,%1,%2,%3};"
        : "+f"(c[0]), "+f"(c[1]), "+f"(c[2]), "+f"(c[3])
        : "r"(a[0]), "r"(a[1]), "r"(a[2]), "r"(a[3]), "r"(b0), "r"(b1));
}

extern __shared__ float s_dyn[];

// ---------------------------------------------------------------------------
// Inner-net path. Block = i, 512 threads, warp = g. fp16 mma (m16n8k16).
// j in quarters of 64 (plog[16]).
// ---------------------------------------------------------------------------
__device__ void inner_path(
    int i,
    const float* __restrict__ z, const float* __restrict__ log_w,
    const float* __restrict__ coeff,   // [2][32]
    const float* __restrict__ w1,      // [1024][64]
    const float* __restrict__ w2,      // [16][64]
    float* __restrict__ out)           // [16][256][256]
{
    uint32_t* ffH2     = (uint32_t*)s_dyn;            // 32 * PADN words
    float*    logits_s = s_dyn + 32 * PADN;           // 16 * 256
    float*    logw_s   = logits_s + 16 * 256;         // 256
    float*    cc       = logw_s + 256;                // 64

    const int tid  = threadIdx.x;
    const int lane = tid & 31;
    const int warp = tid >> 5;

    if (tid < 64) cc[tid] = coeff[tid];
    if (tid < 256) logw_s[tid] = log_w[tid];
    __syncthreads();

    // ---- fourier features: word m packs (ff[2m], ff[2m+1]) ----
    {
        const int j  = tid & 255;
        const int kh = tid >> 8;
        const float zi = z[i];
        const float zj = z[j];
        #pragma unroll
        for (int q = 0; q < 8; q++) {
            const int m = kh * 8 + q;
            float a0 = TWO_PI * fmaf(zi, cc[2 * m],     zj * cc[32 + 2 * m]);
            float a1 = TWO_PI * fmaf(zi, cc[2 * m + 1], zj * cc[32 + 2 * m + 1]);
            float s0, c0, s1, c1;
            __sincosf(a0, &s0, &c0);
            __sincosf(a1, &s1, &c1);
            ffH2[m * PADN + j]        = packh(c0, c1);   // cos pairs: k=2m,2m+1
            ffH2[(16 + m) * PADN + j] = packh(s0, s1);   // sin pairs
        }
    }
    __syncthreads();

    const int g  = warp;
    const int gq = lane >> 2;
    const int T  = lane & 3;
    const float* w1g = w1 + g * (NET_DIM * NET_DIM);
    const float* w2g = w2 + g * NET_DIM;

    for (int h = 0; h < 4; h++) {          // j quarters of 64
        float plog[16];
        #pragma unroll
        for (int e = 0; e < 16; e++) plog[e] = 0.0f;

        for (int mt = 0; mt < 4; mt++) {   // d tiles of 16
            uint32_t A[4][4];
            const float* r0p = w1g + (mt * 16 + gq) * 64;
            const float* r1p = w1g + (mt * 16 + 8 + gq) * 64;
            #pragma unroll
            for (int kk = 0; kk < 4; kk++) {
                float2 v0 = *(const float2*)(r0p + 16 * kk + 2 * T);
                float2 v1 = *(const float2*)(r1p + 16 * kk + 2 * T);
                float2 v2 = *(const float2*)(r0p + 16 * kk + 8 + 2 * T);
                float2 v3 = *(const float2*)(r1p + 16 * kk + 8 + 2 * T);
                A[kk][0] = packh(v0.x, v0.y);
                A[kk][1] = packh(v1.x, v1.y);
                A[kk][2] = packh(v2.x, v2.y);
                A[kk][3] = packh(v3.x, v3.y);
            }
            const float w2a = w2g[mt * 16 + gq];
            const float w2b = w2g[mt * 16 + 8 + gq];

            #pragma unroll
            for (int ntp = 0; ntp < 4; ntp++) {   // 2 n-tiles (16 j) per iter
                const int j0 = h * 64 + ntp * 16;
                float acc0[4] = {0.f, 0.f, 0.f, 0.f};
                float acc1[4] = {0.f, 0.f, 0.f, 0.f};
                #pragma unroll
                for (int kk = 0; kk < 4; kk++) {
                    uint32_t B0a = ffH2[(8 * kk + T)     * PADN + j0 + gq];
                    uint32_t B1a = ffH2[(8 * kk + 4 + T) * PADN + j0 + gq];
                    uint32_t B0b = ffH2[(8 * kk + T)     * PADN + j0 + 8 + gq];
                    uint32_t B1b = ffH2[(8 * kk + 4 + T) * PADN + j0 + 8 + gq];
                    mma_f16(acc0, A[kk], B0a, B1a);
                    mma_f16(acc1, A[kk], B0b, B1b);
                }
                plog[ntp * 4 + 0] += w2a * tanha(acc0[0]) + w2b * tanha(acc0[2]);
                plog[ntp * 4 + 1] += w2a * tanha(acc0[1]) + w2b * tanha(acc0[3]);
                plog[ntp * 4 + 2] += w2a * tanha(acc1[0]) + w2b * tanha(acc1[2]);
                plog[ntp * 4 + 3] += w2a * tanha(acc1[1]) + w2b * tanha(acc1[3]);
            }
        }

        // reduce over d-lanes (gq bits) and store v = lg + log_w
        #pragma unroll
        for (int e = 0; e < 16; e++) {
            float v = plog[e];
            v += __shfl_xor_sync(0xffffffffu, v, 4);
            v += __shfl_xor_sync(0xffffffffu, v, 8);
            v += __shfl_xor_sync(0xffffffffu, v, 16);
            if (lane < 4) {
                const int j = h * 64 + (e >> 2) * 16 + ((e >> 1) & 1) * 8
                            + 2 * T + (e & 1);
                logits_s[g * 256 + j] = -softplus_f(v) + logw_s[j];
            }
        }
    }
    __syncwarp();

    // ---- per-warp logsumexp over j, scatter to out[g][:][i] ----
    {
        float vals[8];
        float mx = -1e30f;
        #pragma unroll
        for (int q = 0; q < 8; q++) {
            vals[q] = logits_s[g * 256 + q * 32 + lane];
            mx = fmaxf(mx, vals[q]);
        }
        mx = warp_max(mx);
        float se = 0.0f;
        #pragma unroll
        for (int q = 0; q < 8; q++) se += __expf(vals[q] - mx);
        se = warp_sum(se);
        const float lse = mx + __logf(se);

        float* og = out + (size_t)g * (NIP * NIP);
        #pragma unroll
        for (int q = 0; q < 8; q++)
            og[(size_t)(q * 32 + lane) * NIP + i] = __expf(vals[q] - lse);
    }
}

// ---------------------------------------------------------------------------
// Input-net path. Block = g, 512 threads. All-fp16 mma.
// ---------------------------------------------------------------------------
__device__ void input_path(
    int g,
    const float* __restrict__ z,
    const float* __restrict__ coeff,   // [32]
    const float* __restrict__ w1,      // [784*64][64]
    const float* __restrict__ w2,      // [784][256][64]
    float* __restrict__ out)           // [784][256][256]
{
    uint32_t* ffH2   = (uint32_t*)s_dyn;               // 32*PADN words
    float*    logits = s_dyn;                          // 32*PADC, alias of ffH2
    uint32_t* hisw   = (uint32_t*)(s_dyn + 32 * PADN); // 256*PH words
    float*    ic     = s_dyn + 32 * PADN + 256 * PH;   // 32

    const int tid  = threadIdx.x;
    const int lane = tid & 31;
    const int warp = tid >> 5;
    const int gq   = lane >> 2;
    const int T    = lane & 3;

    if (tid < 32) ic[tid] = coeff[tid];
    __syncthreads();

    // ---- fourier features ----
    {
        const int n  = tid & 255;
        const int kh = tid >> 8;
        const float zn = z[n];
        #pragma unroll
        for (int q = 0; q < 8; q++) {
            const int m = kh * 8 + q;
            float s0, c0, s1, c1;
            __sincosf(TWO_PI * zn * ic[2 * m],     &s0, &c0);
            __sincosf(TWO_PI * zn * ic[2 * m + 1], &s1, &c1);
            ffH2[m * PADN + n]        = packh(c0, c1);
            ffH2[(16 + m) * PADN + n] = packh(s0, s1);
        }
    }
    __syncthreads();

    // ---- stage 1: H via fp16 mma, write fp16 his[n][d] ----
    {
        const int mt = warp & 3;
        const int nb = warp >> 2;
        const float* w1g = w1 + (size_t)g * 4096;

        uint32_t A1[4][4];
        const float* r0p = w1g + (mt * 16 + gq) * 64;
        const float* r1p = w1g + (mt * 16 + 8 + gq) * 64;
        #pragma unroll
        for (int kk = 0; kk < 4; kk++) {
            float2 v0 = *(const float2*)(r0p + 16 * kk + 2 * T);
            float2 v1 = *(const float2*)(r1p + 16 * kk + 2 * T);
            float2 v2 = *(const float2*)(r0p + 16 * kk + 8 + 2 * T);
            float2 v3 = *(const float2*)(r1p + 16 * kk + 8 + 2 * T);
            A1[kk][0] = packh(v0.x, v0.y);
            A1[kk][1] = packh(v1.x, v1.y);
            A1[kk][2] = packh(v2.x, v2.y);
            A1[kk][3] = packh(v3.x, v3.y);
        }

        __half* hish = (__half*)hisw;
        const int d0 = mt * 16 + gq;

        #pragma unroll
        for (int t = 0; t < 8; t++) {
            const int n0 = nb * 64 + t * 8;
            float acc[4] = {0.f, 0.f, 0.f, 0.f};
            #pragma unroll
            for (int kk = 0; kk < 4; kk++) {
                uint32_t b0 = ffH2[(8 * kk + T)     * PADN + n0 + gq];
                uint32_t b1 = ffH2[(8 * kk + 4 + T) * PADN + n0 + gq];
                mma_f16(acc, A1[kk], b0, b1);
            }
            const int na = n0 + 2 * T;
            hish[na       * (2 * PH) + d0]     = __float2half_rn(tanha(acc[0]));
            hish[(na + 1) * (2 * PH) + d0]     = __float2half_rn(tanha(acc[1]));
            hish[na       * (2 * PH) + d0 + 8] = __float2half_rn(tanha(acc[2]));
            hish[(na + 1) * (2 * PH) + d0 + 8] = __float2half_rn(tanha(acc[3]));
        }
    }
    __syncthreads();   // his done; ffH2 region free -> logits

    // ---- stage 2: logits[n][c] via fp16 mma, W2 in registers ----
    const int cb = warp * 16;
    uint32_t Bw[2][4][2];
    {
        const float* w2g = w2 + (size_t)g * 256 * 64;
        #pragma unroll
        for (int ct = 0; ct < 2; ct++) {
            const float* w2c = w2g + (cb + ct * 8 + gq) * 64;
            #pragma unroll
            for (int kk = 0; kk < 4; kk++) {
                float2 u0 = *(const float2*)(w2c + 16 * kk + 2 * T);
                float2 u1 = *(const float2*)(w2c + 16 * kk + 8 + 2 * T);
                Bw[ct][kk][0] = packh(u0.x, u0.y);
                Bw[ct][kk][1] = packh(u1.x, u1.y);
            }
        }
    }

    float* outg = out + (size_t)g * (NIP * N_CAT);

    for (int pass = 0; pass < 8; pass++) {
        const int n0 = pass * 32;

        #pragma unroll
        for (int mt2 = 0; mt2 < 2; mt2++) {
            const int m0 = n0 + mt2 * 16;
            uint32_t A2[4][4];
            #pragma unroll
            for (int kk = 0; kk < 4; kk++) {
                A2[kk][0] = hisw[(m0 + gq)     * PH + 8 * kk + T];
                A2[kk][1] = hisw[(m0 + 8 + gq) * PH + 8 * kk + T];
                A2[kk][2] = hisw[(m0 + gq)     * PH + 8 * kk + 4 + T];
                A2[kk][3] = hisw[(m0 + 8 + gq) * PH + 8 * kk + 4 + T];
            }
            #pragma unroll
            for (int ct = 0; ct < 2; ct++) {
                float acc[4] = {0.f, 0.f, 0.f, 0.f};
                #pragma unroll
                for (int kk = 0; kk < 4; kk++)
                    mma_f16(acc, A2[kk], Bw[ct][kk][0], Bw[ct][kk][1]);
                const int nl = mt2 * 16 + gq;
                const int cc0 = cb + ct * 8 + 2 * T;
                *(float2*)&logits[nl       * PADC + cc0] = make_float2(acc[0], acc[1]);
                *(float2*)&logits[(nl + 8) * PADC + cc0] = make_float2(acc[2], acc[3]);
            }
        }
        __syncthreads();

        // epilogue: log_softmax over c, 32 c per thread
        {
            const int nl  = tid >> 4;
            const int sub = tid & 15;
            const float* row = logits + nl * PADC;

            float4 v[4];
            float mx = -1e30f;
            #pragma unroll
            for (int q = 0; q < 4; q++) {
                v[q] = *(const float4*)(row + q * 64 + sub * 4);
                mx = fmaxf(mx, fmaxf(fmaxf(v[q].x, v[q].y), fmaxf(v[q].z, v[q].w)));
            }
            #pragma unroll
            for (int o = 1; o < 16; o <<= 1)
                mx = fmaxf(mx, __shfl_xor_sync(0xffffffffu, mx, o));

            float se = 0.0f;
            #pragma unroll
            for (int q = 0; q < 4; q++) {
                se += __expf(v[q].x - mx) + __expf(v[q].y - mx)
                    + __expf(v[q].z - mx) + __expf(v[q].w - mx);
            }
            #pragma unroll
            for (int o = 1; o < 16; o <<= 1)
                se += __shfl_xor_sync(0xffffffffu, se, o);

            const float lse = mx + __logf(se);
            float* orow = outg + (size_t)(n0 + nl) * N_CAT;
            #pragma unroll
            for (int q = 0; q < 4; q++) {
                float4 o4;
                o4.x = v[q].x - lse; o4.y = v[q].y - lse;
                o4.z = v[q].z - lse; o4.w = v[q].w - lse;
                *(float4*)(orow + q * 64 + sub * 4) = o4;
            }
        }
        __syncthreads();
    }
}

// ---------------------------------------------------------------------------
// Fused fat kernel: blocks 0..255 -> inner net (i), 256..1039 -> input net (g)
// ---------------------------------------------------------------------------
__global__ void __launch_bounds__(512, 2) fused_kernel(
    const float* __restrict__ z, const float* __restrict__ log_w,
    const float* __restrict__ inner_coeff,
    const float* __restrict__ inner_w1,
    const float* __restrict__ inner_w2,
    const float* __restrict__ input_coeff,
    const float* __restrict__ input_w1,
    const float* __restrict__ input_w2,
    float* __restrict__ out)
{
    if (blockIdx.x < NIP) {
        inner_path(blockIdx.x, z, log_w, inner_coeff, inner_w1, inner_w2, out);
    } else {
        input_path(blockIdx.x - NIP, z, input_coeff, input_w1, input_w2,
                   out + (size_t)N_INNER * NIP * NIP);
    }
}

// ---------------------------------------------------------------------------
// launch
// ---------------------------------------------------------------------------
extern "C" void kernel_launch(void* const* d_in, const int* in_sizes, int n_in,
                              void* d_out, int out_size) {
    (void)in_sizes; (void)n_in; (void)out_size;
    const float* z           = (const float*)d_in[0];
    const float* log_w       = (const float*)d_in[1];
    const float* inner_coeff = (const float*)d_in[2];
    const float* inner_w1    = (const float*)d_in[3];
    const float* inner_w2    = (const float*)d_in[4];
    const float* input_coeff = (const float*)d_in[5];
    const float* input_w1    = (const float*)d_in[6];
    const float* input_w2    = (const float*)d_in[7];
    float* out = (float*)d_out;

    const int smem_bytes = (32 * PADN + 256 * PH + 32) * (int)sizeof(float);
    cudaFuncSetAttribute(fused_kernel,
                         cudaFuncAttributeMaxDynamicSharedMemorySize, smem_bytes);

    fused_kernel<<<NIP + N_INPUT, 512, smem_bytes>>>(
        z, log_w, inner_coeff, inner_w1, inner_w2,
        input_coeff, input_w1, input_w2, out);
}

// round 8
// speedup vs baseline: 5.2817x; 1.0158x over previous
#include <cuda_runtime.h>
#include <cuda_bf16.h>
#include <cuda_fp16.h>
#include <math.h>
#include <stdint.h>

#define NIP       256
#define N_INNER   16
#define NET_DIM   64
#define N_INPUT   784
#define N_CAT     256
#define TWO_PI    6.283185307179586f

#define PADC  260   // logits row pitch (words)
#define FFQ_P 260   // ff paired-row pitch in uint2 (banks 8T+2gq+{0,1})
#define HISQ_P 20   // his row pitch in uint2 (banks 8gq+2T+{0,1})

// ---------------------------------------------------------------------------
// helpers
// ---------------------------------------------------------------------------
__device__ __forceinline__ float tanha(float x) {
    float y;
    asm("tanh.approx.f32 %0, %1;" : "=f"(y) : "f"(x));
    return y;
}

__device__ __forceinline__ float softplus_f(float x) {
    float ax = fabsf(x);
    return fmaxf(x, 0.0f) + log1pf(__expf(-ax));
}

__device__ __forceinline__ float warp_max(float v) {
    #pragma unroll
    for (int o = 16; o > 0; o >>= 1)
        v = fmaxf(v, __shfl_xor_sync(0xffffffffu, v, o));
    return v;
}

__device__ __forceinline__ float warp_sum(float v) {
    #pragma unroll
    for (int o = 16; o > 0; o >>= 1)
        v += __shfl_xor_sync(0xffffffffu, v, o);
    return v;
}

__device__ __forceinline__ uint32_t packh(float a, float b) {
    __half2 h = __floats2half2_rn(a, b);
    return *(uint32_t*)&h;
}

// fp16 word w (packing halfs 2w,2w+1) -> paired layout (uint2 idx, sel)
// idx = 4*(w>>3) + (w&3), sel = (w>>2)&1
__device__ __forceinline__ int ffq_word_addr(int w, int col) {
    const int idx = 4 * (w >> 3) + (w & 3);
    const int sel = (w >> 2) & 1;
    return (idx * FFQ_P + col) * 2 + sel;
}

// half index d -> half position within paired his row (pitch 80 halfs)
__device__ __forceinline__ int his_half_idx(int d) {
    return (4 * (d >> 4) + ((d >> 1) & 3)) * 4 + ((d >> 3) & 1) * 2 + (d & 1);
}

// D += A(16x16,row) * B(16x8,col), fp16 inputs, fp32 accum
__device__ __forceinline__ void mma_f16(float* c, const uint32_t* a,
                                        uint32_t b0, uint32_t b1) {
    asm volatile(
        "mma.sync.aligned.m16n8k16.row.col.f32.f16.f16.f32 "
        "{%0,%1,%2,%3}, {%4,%5,%6,%7}, {%8,%9}, {%0,%1,%2,%3};"
        : "+f"(c[0]), "+f"(c[1]), "+f"(c[2]), "+f"(c[3])
        : "r"(a[0]), "r"(a[1]), "r"(a[2]), "r"(a[3]), "r"(b0), "r"(b1));
}

extern __shared__ float s_dyn[];

// ---------------------------------------------------------------------------
// Inner-net path. Block = i, 512 threads, warp = g. fp16 mma, LDS.64 B pairs.
// ---------------------------------------------------------------------------
__device__ void inner_path(
    int i,
    const float* __restrict__ z, const float* __restrict__ log_w,
    const float* __restrict__ coeff,   // [2][32]
    const float* __restrict__ w1,      // [1024][64]
    const float* __restrict__ w2,      // [16][64]
    float* __restrict__ out)           // [16][256][256]
{
    uint2*    ffQ      = (uint2*)s_dyn;               // 16 * FFQ_P uint2
    uint32_t* ffW      = (uint32_t*)s_dyn;            // word view for writes
    float*    logits_s = s_dyn + 16 * FFQ_P * 2;      // 16 * 256
    float*    logw_s   = logits_s + 16 * 256;         // 256
    float*    cc       = logw_s + 256;                // 64

    const int tid  = threadIdx.x;
    const int lane = tid & 31;
    const int warp = tid >> 5;

    if (tid < 64) cc[tid] = coeff[tid];
    if (tid < 256) logw_s[tid] = log_w[tid];
    __syncthreads();

    // ---- fourier features: fp16 word m packs (ff[2m], ff[2m+1]) ----
    {
        const int j  = tid & 255;
        const int kh = tid >> 8;
        const float zi = z[i];
        const float zj = z[j];
        #pragma unroll
        for (int q = 0; q < 8; q++) {
            const int m = kh * 8 + q;        // cos word m, sin word 16+m
            float a0 = TWO_PI * fmaf(zi, cc[2 * m],     zj * cc[32 + 2 * m]);
            float a1 = TWO_PI * fmaf(zi, cc[2 * m + 1], zj * cc[32 + 2 * m + 1]);
            float s0, c0, s1, c1;
            __sincosf(a0, &s0, &c0);
            __sincosf(a1, &s1, &c1);
            ffW[ffq_word_addr(m, j)]      = packh(c0, c1);
            ffW[ffq_word_addr(16 + m, j)] = packh(s0, s1);
        }
    }
    __syncthreads();

    const int g  = warp;
    const int gq = lane >> 2;
    const int T  = lane & 3;
    const float* w1g = w1 + g * (NET_DIM * NET_DIM);
    const float* w2g = w2 + g * NET_DIM;

    for (int h = 0; h < 4; h++) {          // j quarters of 64
        float plog[16];
        #pragma unroll
        for (int e = 0; e < 16; e++) plog[e] = 0.0f;

        for (int mt = 0; mt < 4; mt++) {   // d tiles of 16
            uint32_t A[4][4];
            const float* r0p = w1g + (mt * 16 + gq) * 64;
            const float* r1p = w1g + (mt * 16 + 8 + gq) * 64;
            #pragma unroll
            for (int kk = 0; kk < 4; kk++) {
                float2 v0 = *(const float2*)(r0p + 16 * kk + 2 * T);
                float2 v1 = *(const float2*)(r1p + 16 * kk + 2 * T);
                float2 v2 = *(const float2*)(r0p + 16 * kk + 8 + 2 * T);
                float2 v3 = *(const float2*)(r1p + 16 * kk + 8 + 2 * T);
                A[kk][0] = packh(v0.x, v0.y);
                A[kk][1] = packh(v1.x, v1.y);
                A[kk][2] = packh(v2.x, v2.y);
                A[kk][3] = packh(v3.x, v3.y);
            }
            const float w2a = w2g[mt * 16 + gq];
            const float w2b = w2g[mt * 16 + 8 + gq];

            #pragma unroll
            for (int ntp = 0; ntp < 4; ntp++) {   // 2 n-tiles (16 j) per iter
                const int j0 = h * 64 + ntp * 16;
                float acc0[4] = {0.f, 0.f, 0.f, 0.f};
                float acc1[4] = {0.f, 0.f, 0.f, 0.f};
                #pragma unroll
                for (int kk = 0; kk < 4; kk++) {
                    uint2 Ba = ffQ[(4 * kk + T) * FFQ_P + j0 + gq];
                    uint2 Bb = ffQ[(4 * kk + T) * FFQ_P + j0 + 8 + gq];
                    mma_f16(acc0, A[kk], Ba.x, Ba.y);
                    mma_f16(acc1, A[kk], Bb.x, Bb.y);
                }
                plog[ntp * 4 + 0] += w2a * tanha(acc0[0]) + w2b * tanha(acc0[2]);
                plog[ntp * 4 + 1] += w2a * tanha(acc0[1]) + w2b * tanha(acc0[3]);
                plog[ntp * 4 + 2] += w2a * tanha(acc1[0]) + w2b * tanha(acc1[2]);
                plog[ntp * 4 + 3] += w2a * tanha(acc1[1]) + w2b * tanha(acc1[3]);
            }
        }

        // reduce over d-lanes (gq bits) and store v = lg + log_w
        #pragma unroll
        for (int e = 0; e < 16; e++) {
            float v = plog[e];
            v += __shfl_xor_sync(0xffffffffu, v, 4);
            v += __shfl_xor_sync(0xffffffffu, v, 8);
            v += __shfl_xor_sync(0xffffffffu, v, 16);
            if (lane < 4) {
                const int j = h * 64 + (e >> 2) * 16 + ((e >> 1) & 1) * 8
                            + 2 * T + (e & 1);
                logits_s[g * 256 + j] = -softplus_f(v) + logw_s[j];
            }
        }
    }
    __syncwarp();

    // ---- per-warp logsumexp over j, scatter to out[g][:][i] ----
    {
        float vals[8];
        float mx = -1e30f;
        #pragma unroll
        for (int q = 0; q < 8; q++) {
            vals[q] = logits_s[g * 256 + q * 32 + lane];
            mx = fmaxf(mx, vals[q]);
        }
        mx = warp_max(mx);
        float se = 0.0f;
        #pragma unroll
        for (int q = 0; q < 8; q++) se += __expf(vals[q] - mx);
        se = warp_sum(se);
        const float lse = mx + __logf(se);

        float* og = out + (size_t)g * (NIP * NIP);
        #pragma unroll
        for (int q = 0; q < 8; q++)
            og[(size_t)(q * 32 + lane) * NIP + i] = __expf(vals[q] - lse);
    }
}

// ---------------------------------------------------------------------------
// Input-net path. Block = g, 512 threads. All-fp16 mma, LDS.64 pairs.
// ---------------------------------------------------------------------------
__device__ void input_path(
    int g,
    const float* __restrict__ z,
    const float* __restrict__ coeff,   // [32]
    const float* __restrict__ w1,      // [784*64][64]
    const float* __restrict__ w2,      // [784][256][64]
    float* __restrict__ out)           // [784][256][256]
{
    uint2*    ffQ    = (uint2*)s_dyn;                       // 16 * FFQ_P uint2
    uint32_t* ffW    = (uint32_t*)s_dyn;
    float*    logits = s_dyn;                               // 32*PADC, alias
    uint2*    hisQ   = (uint2*)(s_dyn + 16 * FFQ_P * 2);    // 256 * HISQ_P
    __half*   hisH   = (__half*)hisQ;                       // half view (pitch 80)
    float*    ic     = s_dyn + 16 * FFQ_P * 2 + 256 * HISQ_P * 2;  // 32

    const int tid  = threadIdx.x;
    const int lane = tid & 31;
    const int warp = tid >> 5;
    const int gq   = lane >> 2;
    const int T    = lane & 3;

    if (tid < 32) ic[tid] = coeff[tid];
    __syncthreads();

    // ---- fourier features ----
    {
        const int n  = tid & 255;
        const int kh = tid >> 8;
        const float zn = z[n];
        #pragma unroll
        for (int q = 0; q < 8; q++) {
            const int m = kh * 8 + q;
            float s0, c0, s1, c1;
            __sincosf(TWO_PI * zn * ic[2 * m],     &s0, &c0);
            __sincosf(TWO_PI * zn * ic[2 * m + 1], &s1, &c1);
            ffW[ffq_word_addr(m, n)]      = packh(c0, c1);
            ffW[ffq_word_addr(16 + m, n)] = packh(s0, s1);
        }
    }
    __syncthreads();

    // ---- stage 1: H via fp16 mma, write fp16 his (paired layout) ----
    {
        const int mt = warp & 3;
        const int nb = warp >> 2;
        const float* w1g = w1 + (size_t)g * 4096;

        uint32_t A1[4][4];
        const float* r0p = w1g + (mt * 16 + gq) * 64;
        const float* r1p = w1g + (mt * 16 + 8 + gq) * 64;
        #pragma unroll
        for (int kk = 0; kk < 4; kk++) {
            float2 v0 = *(const float2*)(r0p + 16 * kk + 2 * T);
            float2 v1 = *(const float2*)(r1p + 16 * kk + 2 * T);
            float2 v2 = *(const float2*)(r0p + 16 * kk + 8 + 2 * T);
            float2 v3 = *(const float2*)(r1p + 16 * kk + 8 + 2 * T);
            A1[kk][0] = packh(v0.x, v0.y);
            A1[kk][1] = packh(v1.x, v1.y);
            A1[kk][2] = packh(v2.x, v2.y);
            A1[kk][3] = packh(v3.x, v3.y);
        }

        const int d0 = mt * 16 + gq;
        const int hA = his_half_idx(d0);
        const int hB = his_half_idx(d0 + 8);

        #pragma unroll
        for (int t = 0; t < 8; t++) {
            const int n0 = nb * 64 + t * 8;
            float acc[4] = {0.f, 0.f, 0.f, 0.f};
            #pragma unroll
            for (int kk = 0; kk < 4; kk++) {
                uint2 B = ffQ[(4 * kk + T) * FFQ_P + n0 + gq];
                mma_f16(acc, A1[kk], B.x, B.y);
            }
            const int na = n0 + 2 * T;
            hisH[na       * 80 + hA] = __float2half_rn(tanha(acc[0]));
            hisH[(na + 1) * 80 + hA] = __float2half_rn(tanha(acc[1]));
            hisH[na       * 80 + hB] = __float2half_rn(tanha(acc[2]));
            hisH[(na + 1) * 80 + hB] = __float2half_rn(tanha(acc[3]));
        }
    }
    __syncthreads();   // his done; ffQ region free -> logits

    // ---- stage 2: logits[n][c] via fp16 mma, W2 in registers ----
    const int cb = warp * 16;
    uint32_t Bw[2][4][2];
    {
        const float* w2g = w2 + (size_t)g * 256 * 64;
        #pragma unroll
        for (int ct = 0; ct < 2; ct++) {
            const float* w2c = w2g + (cb + ct * 8 + gq) * 64;
            #pragma unroll
            for (int kk = 0; kk < 4; kk++) {
                float2 u0 = *(const float2*)(w2c + 16 * kk + 2 * T);
                float2 u1 = *(const float2*)(w2c + 16 * kk + 8 + 2 * T);
                Bw[ct][kk][0] = packh(u0.x, u0.y);
                Bw[ct][kk][1] = packh(u1.x, u1.y);
            }
        }
    }

    float* outg = out + (size_t)g * (NIP * N_CAT);

    for (int pass = 0; pass < 8; pass++) {
        const int n0 = pass * 32;

        #pragma unroll
        for (int mt2 = 0; mt2 < 2; mt2++) {
            const int m0 = n0 + mt2 * 16;
            uint32_t A2[4][4];
            #pragma unroll
            for (int kk = 0; kk < 4; kk++) {
                uint2 va = hisQ[(m0 + gq)     * HISQ_P + 4 * kk + T];
                uint2 vb = hisQ[(m0 + 8 + gq) * HISQ_P + 4 * kk + T];
                A2[kk][0] = va.x;
                A2[kk][1] = vb.x;
                A2[kk][2] = va.y;
                A2[kk][3] = vb.y;
            }
            #pragma unroll
            for (int ct = 0; ct < 2; ct++) {
                float acc[4] = {0.f, 0.f, 0.f, 0.f};
                #pragma unroll
                for (int kk = 0; kk < 4; kk++)
                    mma_f16(acc, A2[kk], Bw[ct][kk][0], Bw[ct][kk][1]);
                const int nl = mt2 * 16 + gq;
                const int cc0 = cb + ct * 8 + 2 * T;
                *(float2*)&logits[nl       * PADC + cc0] = make_float2(acc[0], acc[1]);
                *(float2*)&logits[(nl + 8) * PADC + cc0] = make_float2(acc[2], acc[3]);
            }
        }
        __syncthreads();

        // epilogue: log_softmax over c, 32 c per thread
        {
            const int nl  = tid >> 4;
            const int sub = tid & 15;
            const float* row = logits + nl * PADC;

            float4 v[4];
            float mx = -1e30f;
            #pragma unroll
            for (int q = 0; q < 4; q++) {
                v[q] = *(const float4*)(row + q * 64 + sub * 4);
                mx = fmaxf(mx, fmaxf(fmaxf(v[q].x, v[q].y), fmaxf(v[q].z, v[q].w)));
            }
            #pragma unroll
            for (int o = 1; o < 16; o <<= 1)
                mx = fmaxf(mx, __shfl_xor_sync(0xffffffffu, mx, o));

            float se = 0.0f;
            #pragma unroll
            for (int q = 0; q < 4; q++) {
                se += __expf(v[q].x - mx) + __expf(v[q].y - mx)
                    + __expf(v[q].z - mx) + __expf(v[q].w - mx);
            }
            #pragma unroll
            for (int o = 1; o < 16; o <<= 1)
                se += __shfl_xor_sync(0xffffffffu, se, o);

            const float lse = mx + __logf(se);
            float* orow = outg + (size_t)(n0 + nl) * N_CAT;
            #pragma unroll
            for (int q = 0; q < 4; q++) {
                float4 o4;
                o4.x = v[q].x - lse; o4.y = v[q].y - lse;
                o4.z = v[q].z - lse; o4.w = v[q].w - lse;
                *(float4*)(orow + q * 64 + sub * 4) = o4;
            }
        }
        __syncthreads();
    }
}

// ---------------------------------------------------------------------------
// Fused fat kernel: blocks 0..255 -> inner net (i), 256..1039 -> input net (g)
// ---------------------------------------------------------------------------
__global__ void __launch_bounds__(512, 2) fused_kernel(
    const float* __restrict__ z, const float* __restrict__ log_w,
    const float* __restrict__ inner_coeff,
    const float* __restrict__ inner_w1,
    const float* __restrict__ inner_w2,
    const float* __restrict__ input_coeff,
    const float* __restrict__ input_w1,
    const float* __restrict__ input_w2,
    float* __restrict__ out)
{
    if (blockIdx.x < NIP) {
        inner_path(blockIdx.x, z, log_w, inner_coeff, inner_w1, inner_w2, out);
    } else {
        input_path(blockIdx.x - NIP, z, input_coeff, input_w1, input_w2,
                   out + (size_t)N_INNER * NIP * NIP);
    }
}

// ---------------------------------------------------------------------------
// launch
// ---------------------------------------------------------------------------
extern "C" void kernel_launch(void* const* d_in, const int* in_sizes, int n_in,
                              void* d_out, int out_size) {
    (void)in_sizes; (void)n_in; (void)out_size;
    const float* z           = (const float*)d_in[0];
    const float* log_w       = (const float*)d_in[1];
    const float* inner_coeff = (const float*)d_in[2];
    const float* inner_w1    = (const float*)d_in[3];
    const float* inner_w2    = (const float*)d_in[4];
    const float* input_coeff = (const float*)d_in[5];
    const float* input_w1    = (const float*)d_in[6];
    const float* input_w2    = (const float*)d_in[7];
    float* out = (float*)d_out;

    // input path is the larger user: ffQ (16*FFQ_P uint2) + hisQ (256*HISQ_P uint2) + ic
    const int smem_bytes = (16 * FFQ_P * 2 + 256 * HISQ_P * 2 + 32) * (int)sizeof(float);
    cudaFuncSetAttribute(fused_kernel,
                         cudaFuncAttributeMaxDynamicSharedMemorySize, smem_bytes);

    fused_kernel<<<NIP + N_INPUT, 512, smem_bytes>>>(
        z, log_w, inner_coeff, inner_w1, inner_w2,
        input_coeff, input_w1, input_w2, out);
}